// round 1
// baseline (speedup 1.0000x reference)
#include <cuda_runtime.h>
#include <math.h>

#define EMB 1024
#define SEQ 2048
#define BATCH 2
#define NH 16
#define HD 64
#define FF_DIM 2048
#define MROWS (BATCH * SEQ)   // 4096
#define LN_EPS 1e-5f

// ---------------- scratch (device globals; no runtime allocation) ----------------
__device__ float g_qkv[(size_t)MROWS * 3 * EMB];   // [4096, 3072]
__device__ float g_attn[(size_t)MROWS * EMB];      // attention output (head-concat)
__device__ float g_tmp[(size_t)MROWS * EMB];       // proj / ff2 output
__device__ float g_x1[(size_t)MROWS * EMB];        // post-LN1
__device__ float g_ffh[(size_t)MROWS * FF_DIM];    // relu(x1 @ Wff1 + b)

// ---------------- generic tiled SGEMM: C = A[M,K] @ B[K,N] + bias, optional relu ----
// BM=BN=128, BK=8, 256 threads, 8x8 microtile per thread. All dims divide evenly.
__global__ __launch_bounds__(256) void gemm_kernel(
    const float* __restrict__ A, const float* __restrict__ B,
    const float* __restrict__ bias, float* __restrict__ C,
    int M, int N, int K, int relu)
{
    __shared__ float As[8][128];
    __shared__ float Bs[8][128];

    const int tid = threadIdx.x;
    const int bx = blockIdx.x, by = blockIdx.y;
    const int ty = tid >> 4, tx = tid & 15;

    const int arow = tid >> 1;            // 0..127
    const int acol = (tid & 1) * 4;       // 0 or 4
    const int brow = tid >> 5;            // 0..7
    const int bcol = (tid & 31) * 4;      // 0..124

    const float* Aptr = A + (size_t)(by * 128 + arow) * K + acol;
    const float* Bptr = B + (size_t)brow * N + bx * 128 + bcol;

    float acc[8][8];
    #pragma unroll
    for (int i = 0; i < 8; i++)
        #pragma unroll
        for (int j = 0; j < 8; j++) acc[i][j] = 0.f;

    for (int k0 = 0; k0 < K; k0 += 8) {
        float4 av = *(const float4*)(Aptr + k0);
        float4 bv = *(const float4*)(Bptr + (size_t)k0 * N);
        As[acol + 0][arow] = av.x;
        As[acol + 1][arow] = av.y;
        As[acol + 2][arow] = av.z;
        As[acol + 3][arow] = av.w;
        *(float4*)&Bs[brow][bcol] = bv;
        __syncthreads();

        #pragma unroll
        for (int k = 0; k < 8; k++) {
            float a[8], b[8];
            *(float4*)(a)     = *(const float4*)&As[k][ty * 8];
            *(float4*)(a + 4) = *(const float4*)&As[k][ty * 8 + 4];
            *(float4*)(b)     = *(const float4*)&Bs[k][tx * 8];
            *(float4*)(b + 4) = *(const float4*)&Bs[k][tx * 8 + 4];
            #pragma unroll
            for (int i = 0; i < 8; i++)
                #pragma unroll
                for (int j = 0; j < 8; j++)
                    acc[i][j] = fmaf(a[i], b[j], acc[i][j]);
        }
        __syncthreads();
    }

    const int col0 = bx * 128 + tx * 8;
    #pragma unroll
    for (int i = 0; i < 8; i++) {
        const int row = by * 128 + ty * 8 + i;
        float out[8];
        #pragma unroll
        for (int j = 0; j < 8; j++) {
            float v = acc[i][j] + bias[col0 + j];
            if (relu) v = fmaxf(v, 0.f);
            out[j] = v;
        }
        float* cp = C + (size_t)row * N + col0;
        *(float4*)(cp)     = *(float4*)(out);
        *(float4*)(cp + 4) = *(float4*)(out + 4);
    }
}

// ---------------- flash attention (causal), one CTA per (b, h, 64-row q tile) ------
// SMEM: Qs[64][64] d-major, KVs[64][64] (K d-major, then V k-major), S stride 65.
__global__ __launch_bounds__(256) void attn_kernel(
    const float* __restrict__ qkv, float* __restrict__ Hout)
{
    extern __shared__ float sm[];
    float* Qs   = sm;                    // 4096 floats: Qs[d*64 + i]
    float* KVs  = sm + 4096;             // 4096 floats
    float* S    = sm + 8192;             // 64*65 floats, S[r*65 + c]
    float* corr = S + 64 * 65;           // 64
    float* linv = corr + 64;             // 64

    const int tid = threadIdx.x;
    const int qt = blockIdx.x, h = blockIdx.y, b = blockIdx.z;
    const int q0 = qt * 64;
    const float* base = qkv + (size_t)b * SEQ * 3 * EMB;
    const int ty = tid >> 4, tx = tid & 15;

    // load Q tile (pre-scaled by 1/sqrt(64))
    for (int idx = tid; idx < 4096; idx += 256) {
        int i = idx >> 6, d = idx & 63;
        Qs[d * 64 + i] = base[(size_t)(q0 + i) * (3 * EMB) + h * HD + d] * 0.125f;
    }

    float m = -INFINITY, l = 0.f;   // valid for tid < 64 (row tid)
    float O[4][4];
    #pragma unroll
    for (int i = 0; i < 4; i++)
        #pragma unroll
        for (int j = 0; j < 4; j++) O[i][j] = 0.f;

    for (int k0 = 0; k0 <= q0; k0 += 64) {
        __syncthreads();   // previous iter's V / S reads done before overwrite
        // load K tile, d-major: KVs[d*64 + c]
        for (int idx = tid; idx < 4096; idx += 256) {
            int c = idx >> 6, d = idx & 63;
            KVs[d * 64 + c] = base[(size_t)(k0 + c) * (3 * EMB) + EMB + h * HD + d];
        }
        __syncthreads();

        // S = Q K^T (pre-scaled)
        float acc[4][4];
        #pragma unroll
        for (int i = 0; i < 4; i++)
            #pragma unroll
            for (int j = 0; j < 4; j++) acc[i][j] = 0.f;
        #pragma unroll 8
        for (int d = 0; d < 64; d++) {
            float a[4], bb[4];
            *(float4*)a  = *(const float4*)&Qs[d * 64 + ty * 4];
            *(float4*)bb = *(const float4*)&KVs[d * 64 + tx * 4];
            #pragma unroll
            for (int i = 0; i < 4; i++)
                #pragma unroll
                for (int j = 0; j < 4; j++)
                    acc[i][j] = fmaf(a[i], bb[j], acc[i][j]);
        }
        #pragma unroll
        for (int i = 0; i < 4; i++)
            #pragma unroll
            for (int j = 0; j < 4; j++)
                S[(ty * 4 + i) * 65 + tx * 4 + j] = acc[i][j];
        __syncthreads();

        // online softmax, one thread per row
        if (tid < 64) {
            const int lim = (k0 == q0) ? tid : 63;   // causal limit within tile
            float mx = -INFINITY;
            for (int c = 0; c <= lim; c++) mx = fmaxf(mx, S[tid * 65 + c]);
            const float mnew = fmaxf(m, mx);
            const float cr = __expf(m - mnew);
            float s = 0.f;
            for (int c = 0; c <= lim; c++) {
                float e = __expf(S[tid * 65 + c] - mnew);
                S[tid * 65 + c] = e;
                s += e;
            }
            for (int c = lim + 1; c < 64; c++) S[tid * 65 + c] = 0.f;
            l = l * cr + s;
            m = mnew;
            corr[tid] = cr;
        }
        __syncthreads();

        // load V tile, k-major: KVs[k*64 + c]
        for (int idx = tid; idx < 4096; idx += 256) {
            int kk = idx >> 6, c = idx & 63;
            KVs[kk * 64 + c] = base[(size_t)(k0 + kk) * (3 * EMB) + 2 * EMB + h * HD + c];
        }
        __syncthreads();

        // O = O * corr + P @ V
        float cr[4];
        #pragma unroll
        for (int i = 0; i < 4; i++) cr[i] = corr[ty * 4 + i];
        #pragma unroll
        for (int i = 0; i < 4; i++)
            #pragma unroll
            for (int j = 0; j < 4; j++) O[i][j] *= cr[i];
        #pragma unroll 8
        for (int k = 0; k < 64; k++) {
            float p[4], v[4];
            #pragma unroll
            for (int i = 0; i < 4; i++) p[i] = S[(ty * 4 + i) * 65 + k];
            *(float4*)v = *(const float4*)&KVs[k * 64 + tx * 4];
            #pragma unroll
            for (int i = 0; i < 4; i++)
                #pragma unroll
                for (int j = 0; j < 4; j++)
                    O[i][j] = fmaf(p[i], v[j], O[i][j]);
        }
    }

    if (tid < 64) linv[tid] = 1.f / l;
    __syncthreads();

    #pragma unroll
    for (int i = 0; i < 4; i++) {
        const int r = ty * 4 + i;
        const float inv = linv[r];
        float* op = Hout + (size_t)(b * SEQ + q0 + r) * EMB + h * HD + tx * 4;
        float out[4];
        #pragma unroll
        for (int j = 0; j < 4; j++) out[j] = O[i][j] * inv;
        *(float4*)op = *(float4*)out;
    }
}

// ---------------- residual add + layernorm, one block per row ----------------------
__global__ __launch_bounds__(256) void ln_kernel(
    const float* __restrict__ x, const float* __restrict__ hres,
    const float* __restrict__ g, const float* __restrict__ be,
    float* __restrict__ out)
{
    __shared__ float buf[EMB];
    __shared__ float red[8];
    const int row = blockIdx.x;
    const int tid = threadIdx.x;
    const float* xr = x + (size_t)row * EMB;
    const float* hr = hres + (size_t)row * EMB;

    float s = 0.f;
    for (int e = tid; e < EMB; e += 256) {
        float v = xr[e] + hr[e];
        buf[e] = v;
        s += v;
    }
    // block reduce sum
    #pragma unroll
    for (int o = 16; o; o >>= 1) s += __shfl_down_sync(0xffffffffu, s, o);
    if ((tid & 31) == 0) red[tid >> 5] = s;
    __syncthreads();
    if (tid < 8) {
        s = red[tid];
        #pragma unroll
        for (int o = 4; o; o >>= 1) s += __shfl_down_sync(0xffu, s, o);
        if (tid == 0) red[0] = s;
    }
    __syncthreads();
    const float mu = red[0] * (1.f / EMB);
    __syncthreads();

    float vs = 0.f;
    for (int e = tid; e < EMB; e += 256) {
        float d = buf[e] - mu;
        vs += d * d;
    }
    #pragma unroll
    for (int o = 16; o; o >>= 1) vs += __shfl_down_sync(0xffffffffu, vs, o);
    if ((tid & 31) == 0) red[tid >> 5] = vs;
    __syncthreads();
    if (tid < 8) {
        vs = red[tid];
        #pragma unroll
        for (int o = 4; o; o >>= 1) vs += __shfl_down_sync(0xffu, vs, o);
        if (tid == 0) red[0] = vs;
    }
    __syncthreads();
    const float rstd = rsqrtf(red[0] * (1.f / EMB) + LN_EPS);

    for (int e = tid; e < EMB; e += 256)
        out[(size_t)row * EMB + e] = (buf[e] - mu) * rstd * g[e] + be[e];
}

// ---------------- launch ------------------------------------------------------------
extern "C" void kernel_launch(void* const* d_in, const int* in_sizes, int n_in,
                              void* d_out, int out_size)
{
    const float* x     = (const float*)d_in[0];
    const float* W_qkv = (const float*)d_in[1];
    const float* b_qkv = (const float*)d_in[2];
    const float* W_out = (const float*)d_in[3];
    const float* b_out = (const float*)d_in[4];
    const float* g1    = (const float*)d_in[5];
    const float* be1   = (const float*)d_in[6];
    const float* W_ff1 = (const float*)d_in[7];
    const float* b_ff1 = (const float*)d_in[8];
    const float* W_ff2 = (const float*)d_in[9];
    const float* b_ff2 = (const float*)d_in[10];
    const float* g2    = (const float*)d_in[11];
    const float* be2   = (const float*)d_in[12];
    float* out = (float*)d_out;

    float *qkv, *attn, *tmp, *x1, *ffh;
    cudaGetSymbolAddress((void**)&qkv,  g_qkv);
    cudaGetSymbolAddress((void**)&attn, g_attn);
    cudaGetSymbolAddress((void**)&tmp,  g_tmp);
    cudaGetSymbolAddress((void**)&x1,   g_x1);
    cudaGetSymbolAddress((void**)&ffh,  g_ffh);

    const int attn_smem = (4096 + 4096 + 64 * 65 + 64 + 64) * (int)sizeof(float);
    cudaFuncSetAttribute(attn_kernel, cudaFuncAttributeMaxDynamicSharedMemorySize,
                         attn_smem);

    // 1) qkv = x @ W_qkv + b_qkv          [4096, 3072]
    gemm_kernel<<<dim3(3 * EMB / 128, MROWS / 128), 256>>>(
        x, W_qkv, b_qkv, qkv, MROWS, 3 * EMB, EMB, 0);

    // 2) causal attention -> attn [4096, 1024] (head-concat layout)
    attn_kernel<<<dim3(SEQ / 64, NH, BATCH), 256, attn_smem>>>(qkv, attn);

    // 3) proj = attn @ W_out + b_out
    gemm_kernel<<<dim3(EMB / 128, MROWS / 128), 256>>>(
        attn, W_out, b_out, tmp, MROWS, EMB, EMB, 0);

    // 4) x1 = LN(x + proj)
    ln_kernel<<<MROWS, 256>>>(x, tmp, g1, be1, x1);

    // 5) ffh = relu(x1 @ W_ff1 + b_ff1)   [4096, 2048]
    gemm_kernel<<<dim3(FF_DIM / 128, MROWS / 128), 256>>>(
        x1, W_ff1, b_ff1, ffh, MROWS, FF_DIM, EMB, 1);

    // 6) ff = ffh @ W_ff2 + b_ff2
    gemm_kernel<<<dim3(EMB / 128, MROWS / 128), 256>>>(
        ffh, W_ff2, b_ff2, tmp, MROWS, EMB, FF_DIM, 0);

    // 7) out = LN(x1 + ff)
    ln_kernel<<<MROWS, 256>>>(x1, tmp, g2, be2, out);
}

// round 4
// speedup vs baseline: 1.6814x; 1.6814x over previous
#include <cuda_runtime.h>
#include <cuda_bf16.h>
#include <math.h>
#include <stdint.h>

#define EMB 1024
#define SEQ 2048
#define BATCH 2
#define NH 16
#define HD 64
#define FF_DIM 2048
#define MROWS (BATCH * SEQ)   // 4096
#define LN_EPS 1e-5f

// ================= helpers (baseline PTX ISA only: sm_80-era) =================
__device__ __forceinline__ uint32_t smem_u32(const void* p) {
    uint32_t a;
    asm("{ .reg .u64 t; cvta.to.shared.u64 t, %1; cvt.u32.u64 %0, t; }" : "=r"(a) : "l"(p));
    return a;
}
__device__ __forceinline__ uint32_t sw128(uint32_t off) { return off ^ ((off >> 3) & 0x70); }
__device__ __forceinline__ uint32_t pack_bf16(float a, float b) {
    __nv_bfloat162 t = __floats2bfloat162_rn(a, b);
    return *(uint32_t*)&t;
}

#define CP16(dst, src) asm volatile("cp.async.cg.shared.global [%0], [%1], 16;" :: "r"(dst), "l"(src) : "memory")
#define CP_COMMIT()    asm volatile("cp.async.commit_group;" ::: "memory")
#define CP_WAIT0()     asm volatile("cp.async.wait_group 0;" ::: "memory")

#define LDSM4(r, addr) \
    asm volatile("ldmatrix.sync.aligned.m8n8.x4.shared.b16 {%0,%1,%2,%3}, [%4];" \
        : "=r"((r)[0]), "=r"((r)[1]), "=r"((r)[2]), "=r"((r)[3]) : "r"(addr))

#define MMA16816(d, a, b0, b1) \
    asm volatile("mma.sync.aligned.m16n8k16.row.col.f32.bf16.bf16.f32 " \
        "{%0,%1,%2,%3},{%4,%5,%6,%7},{%8,%9},{%0,%1,%2,%3};" \
        : "+f"((d)[0]), "+f"((d)[1]), "+f"((d)[2]), "+f"((d)[3]) \
        : "r"((a)[0]), "r"((a)[1]), "r"((a)[2]), "r"((a)[3]), "r"(b0), "r"(b1))

// ================= scratch =================
__device__ float g_qkv[(size_t)MROWS * 3 * EMB];
__device__ float g_attn[(size_t)MROWS * EMB];
__device__ float g_tmp[(size_t)MROWS * EMB];
__device__ float g_x1[(size_t)MROWS * EMB];
__device__ float g_ffh[(size_t)MROWS * FF_DIM];
__device__ __nv_bfloat16 wt_qkv_h[(size_t)3 * EMB * EMB], wt_qkv_l[(size_t)3 * EMB * EMB];
__device__ __nv_bfloat16 wt_out_h[(size_t)EMB * EMB],     wt_out_l[(size_t)EMB * EMB];
__device__ __nv_bfloat16 wt_ff1_h[(size_t)FF_DIM * EMB],  wt_ff1_l[(size_t)FF_DIM * EMB];
__device__ __nv_bfloat16 wt_ff2_h[(size_t)EMB * FF_DIM],  wt_ff2_l[(size_t)EMB * FF_DIM];

// ============ weight transpose + bf16 hi/lo split: W[K,N] -> T[N,K] ============
__global__ __launch_bounds__(256) void wconv_kernel(
    const float* __restrict__ W, __nv_bfloat16* __restrict__ Th,
    __nv_bfloat16* __restrict__ Tl, int K, int N)
{
    __shared__ float sm[32][33];
    const int tx = threadIdx.x, ty = threadIdx.y;
    const int n0 = blockIdx.x * 32, k0 = blockIdx.y * 32;
    #pragma unroll
    for (int i = 0; i < 4; i++)
        sm[ty + i * 8][tx] = W[(size_t)(k0 + ty + i * 8) * N + n0 + tx];
    __syncthreads();
    #pragma unroll
    for (int i = 0; i < 4; i++) {
        int nl = ty + i * 8;
        float v = sm[tx][nl];
        __nv_bfloat16 h = __float2bfloat16_rn(v);
        __nv_bfloat16 l = __float2bfloat16_rn(v - __bfloat162float(h));
        size_t o = (size_t)(n0 + nl) * K + k0 + tx;
        Th[o] = h;
        Tl[o] = l;
    }
}

// ============ bf16-split HMMA GEMM: C[M,N] = A[M,K] @ T[N,K]^T + bias ============
// CTA tile 128x128, BK=64, double-buffered. 8 warps (4 M x 2 N), warp tile 32x64.
// 3 mma passes per fragment: AhBh + AhBl + AlBh (fp32 accum).
#define ST_BYTES 65536        // per stage: Ah 16K | Al 16K | Bh 16K | Bl 16K
#define OFF_AH 0
#define OFF_AL 16384
#define OFF_BH 32768
#define OFF_BL 49152
#define GEMM_SMEM (2 * ST_BYTES)

__device__ __forceinline__ void gemm_ldA(
    float4 (&r)[8], const float* __restrict__ A, int K, int m0, int kc, int tid)
{
    #pragma unroll
    for (int it = 0; it < 8; it++) {
        int idx = it * 256 + tid;
        int row = idx >> 4, c4 = idx & 15;
        r[it] = *(const float4*)(A + (size_t)(m0 + row) * K + kc + c4 * 4);
    }
}
__device__ __forceinline__ void gemm_stsA(
    const float4 (&r)[8], char* smst, int tid)
{
    #pragma unroll
    for (int it = 0; it < 8; it++) {
        int idx = it * 256 + tid;
        int row = idx >> 4, c4 = idx & 15;
        uint32_t sw = sw128((uint32_t)(row * 128 + c4 * 8));
        float4 v = r[it];
        __nv_bfloat16 h0 = __float2bfloat16_rn(v.x), h1 = __float2bfloat16_rn(v.y);
        __nv_bfloat16 h2 = __float2bfloat16_rn(v.z), h3 = __float2bfloat16_rn(v.w);
        uint2 hh = make_uint2(pack_bf16(__bfloat162float(h0), __bfloat162float(h1)),
                              pack_bf16(__bfloat162float(h2), __bfloat162float(h3)));
        // pack hi exactly (bit-preserving)
        __nv_bfloat162 p0; p0.x = h0; p0.y = h1;
        __nv_bfloat162 p1; p1.x = h2; p1.y = h3;
        hh = make_uint2(*(uint32_t*)&p0, *(uint32_t*)&p1);
        uint2 ll = make_uint2(
            pack_bf16(v.x - __bfloat162float(h0), v.y - __bfloat162float(h1)),
            pack_bf16(v.z - __bfloat162float(h2), v.w - __bfloat162float(h3)));
        *(uint2*)(smst + OFF_AH + sw) = hh;
        *(uint2*)(smst + OFF_AL + sw) = ll;
    }
}
__device__ __forceinline__ void gemm_cpB(
    const __nv_bfloat16* __restrict__ Bh, const __nv_bfloat16* __restrict__ Bl,
    uint32_t sdst, int K, int n0, int kc, int tid)
{
    #pragma unroll
    for (int it = 0; it < 4; it++) {
        int idx = it * 256 + tid;
        int row = idx >> 3, ch = idx & 7;
        uint32_t sw = sw128((uint32_t)(row * 128 + ch * 16));
        const __nv_bfloat16* gh = Bh + (size_t)(n0 + row) * K + kc + ch * 8;
        const __nv_bfloat16* gl = Bl + (size_t)(n0 + row) * K + kc + ch * 8;
        CP16(sdst + OFF_BH + sw, gh);
        CP16(sdst + OFF_BL + sw, gl);
    }
    CP_COMMIT();
}

__global__ __launch_bounds__(256, 1) void gemm_mma(
    const float* __restrict__ A, const __nv_bfloat16* __restrict__ Bh,
    const __nv_bfloat16* __restrict__ Bl, const float* __restrict__ bias,
    float* __restrict__ C, int M, int N, int K, int relu)
{
    extern __shared__ char sm[];
    const uint32_t smb = smem_u32(sm);
    const int tid = threadIdx.x;
    const int wid = tid >> 5, lane = tid & 31;
    const int m0 = blockIdx.y * 128, n0 = blockIdx.x * 128;
    const int wm = (wid & 3) * 32, wn = (wid >> 2) * 64;
    const int NC = K >> 6;

    float acc[2][8][4];
    #pragma unroll
    for (int i = 0; i < 2; i++)
        #pragma unroll
        for (int j = 0; j < 8; j++)
            #pragma unroll
            for (int q = 0; q < 4; q++) acc[i][j][q] = 0.f;

    float4 ra[8];
    // prologue: chunk 0 -> stage 0
    gemm_cpB(Bh, Bl, smb, K, n0, 0, tid);
    gemm_ldA(ra, A, K, m0, 0, tid);
    gemm_stsA(ra, sm, tid);
    CP_WAIT0();
    __syncthreads();

    for (int c = 0; c < NC; c++) {
        const int cur = c & 1;
        const bool more = (c + 1 < NC);
        if (more) {
            gemm_cpB(Bh, Bl, smb + (cur ^ 1) * ST_BYTES, K, n0, (c + 1) << 6, tid);
            gemm_ldA(ra, A, K, m0, (c + 1) << 6, tid);
        }
        // compute chunk c from stage cur
        const uint32_t s0 = smb + cur * ST_BYTES;
        #pragma unroll
        for (int kk = 0; kk < 4; kk++) {
            uint32_t ah[2][4], al[2][4];
            #pragma unroll
            for (int mt = 0; mt < 2; mt++) {
                int row = wm + mt * 16 + (lane & 15);
                uint32_t cbhi = (uint32_t)(kk * 2 + (lane >> 4));
                uint32_t off = (uint32_t)(row * 128) + ((cbhi ^ (row & 7)) << 4);
                LDSM4(ah[mt], s0 + OFF_AH + off);
                LDSM4(al[mt], s0 + OFF_AL + off);
            }
            #pragma unroll
            for (int g = 0; g < 4; g++) {
                int nrow = wn + g * 16 + ((lane >> 4) << 3) + (lane & 7);
                uint32_t cbhi = (uint32_t)(kk * 2 + ((lane >> 3) & 1));
                uint32_t off = (uint32_t)(nrow * 128) + ((cbhi ^ (nrow & 7)) << 4);
                uint32_t bh[4], bl[4];
                LDSM4(bh, s0 + OFF_BH + off);
                LDSM4(bl, s0 + OFF_BL + off);
                #pragma unroll
                for (int mt = 0; mt < 2; mt++) {
                    MMA16816(acc[mt][2 * g],     ah[mt], bh[0], bh[1]);
                    MMA16816(acc[mt][2 * g + 1], ah[mt], bh[2], bh[3]);
                    MMA16816(acc[mt][2 * g],     ah[mt], bl[0], bl[1]);
                    MMA16816(acc[mt][2 * g + 1], ah[mt], bl[2], bl[3]);
                    MMA16816(acc[mt][2 * g],     al[mt], bh[0], bh[1]);
                    MMA16816(acc[mt][2 * g + 1], al[mt], bh[2], bh[3]);
                }
            }
        }
        __syncthreads();
        if (more) {
            gemm_stsA(ra, sm + (cur ^ 1) * ST_BYTES, tid);
            CP_WAIT0();
            __syncthreads();
        }
    }

    // epilogue: bias + optional relu, direct float2 stores
    #pragma unroll
    for (int mt = 0; mt < 2; mt++) {
        #pragma unroll
        for (int nt = 0; nt < 8; nt++) {
            int r0 = m0 + wm + mt * 16 + (lane >> 2);
            int col = n0 + wn + nt * 8 + (lane & 3) * 2;
            float2 bb = *(const float2*)(bias + col);
            float v0 = acc[mt][nt][0] + bb.x;
            float v1 = acc[mt][nt][1] + bb.y;
            float v2 = acc[mt][nt][2] + bb.x;
            float v3 = acc[mt][nt][3] + bb.y;
            if (relu) {
                v0 = fmaxf(v0, 0.f); v1 = fmaxf(v1, 0.f);
                v2 = fmaxf(v2, 0.f); v3 = fmaxf(v3, 0.f);
            }
            float2 o0 = make_float2(v0, v1), o1 = make_float2(v2, v3);
            *(float2*)(C + (size_t)r0 * N + col) = o0;
            *(float2*)(C + (size_t)(r0 + 8) * N + col) = o1;
        }
    }
}

// ================= flash attention (fp32) =================
__global__ __launch_bounds__(256) void attn_kernel(
    const float* __restrict__ qkv, float* __restrict__ Hout)
{
    extern __shared__ float smf[];
    float* Qs = smf;
    float* KVs = smf + 4096;
    float* S = smf + 8192;
    float* corr = S + 64 * 65;
    float* linv = corr + 64;

    const int tid = threadIdx.x;
    const int qt = blockIdx.x, h = blockIdx.y, b = blockIdx.z;
    const int q0 = qt * 64;
    const float* base = qkv + (size_t)b * SEQ * 3 * EMB;
    const int ty = tid >> 4, tx = tid & 15;

    for (int idx = tid; idx < 4096; idx += 256) {
        int i = idx >> 6, d = idx & 63;
        Qs[d * 64 + i] = base[(size_t)(q0 + i) * (3 * EMB) + h * HD + d] * 0.125f;
    }

    float m = -INFINITY, l = 0.f;
    float O[4][4];
    #pragma unroll
    for (int i = 0; i < 4; i++)
        #pragma unroll
        for (int j = 0; j < 4; j++) O[i][j] = 0.f;

    for (int k0 = 0; k0 <= q0; k0 += 64) {
        __syncthreads();
        for (int idx = tid; idx < 4096; idx += 256) {
            int c = idx >> 6, d = idx & 63;
            KVs[d * 64 + c] = base[(size_t)(k0 + c) * (3 * EMB) + EMB + h * HD + d];
        }
        __syncthreads();

        float acc[4][4];
        #pragma unroll
        for (int i = 0; i < 4; i++)
            #pragma unroll
            for (int j = 0; j < 4; j++) acc[i][j] = 0.f;
        #pragma unroll 8
        for (int d = 0; d < 64; d++) {
            float a[4], bb[4];
            *(float4*)a  = *(const float4*)&Qs[d * 64 + ty * 4];
            *(float4*)bb = *(const float4*)&KVs[d * 64 + tx * 4];
            #pragma unroll
            for (int i = 0; i < 4; i++)
                #pragma unroll
                for (int j = 0; j < 4; j++)
                    acc[i][j] = fmaf(a[i], bb[j], acc[i][j]);
        }
        #pragma unroll
        for (int i = 0; i < 4; i++)
            #pragma unroll
            for (int j = 0; j < 4; j++)
                S[(ty * 4 + i) * 65 + tx * 4 + j] = acc[i][j];
        __syncthreads();

        if (tid < 64) {
            const int lim = (k0 == q0) ? tid : 63;
            float mx = -INFINITY;
            for (int c = 0; c <= lim; c++) mx = fmaxf(mx, S[tid * 65 + c]);
            const float mnew = fmaxf(m, mx);
            const float cr = __expf(m - mnew);
            float s = 0.f;
            for (int c = 0; c <= lim; c++) {
                float e = __expf(S[tid * 65 + c] - mnew);
                S[tid * 65 + c] = e;
                s += e;
            }
            for (int c = lim + 1; c < 64; c++) S[tid * 65 + c] = 0.f;
            l = l * cr + s;
            m = mnew;
            corr[tid] = cr;
        }
        __syncthreads();

        for (int idx = tid; idx < 4096; idx += 256) {
            int kk = idx >> 6, c = idx & 63;
            KVs[kk * 64 + c] = base[(size_t)(k0 + kk) * (3 * EMB) + 2 * EMB + h * HD + c];
        }
        __syncthreads();

        float cr[4];
        #pragma unroll
        for (int i = 0; i < 4; i++) cr[i] = corr[ty * 4 + i];
        #pragma unroll
        for (int i = 0; i < 4; i++)
            #pragma unroll
            for (int j = 0; j < 4; j++) O[i][j] *= cr[i];
        #pragma unroll 8
        for (int k = 0; k < 64; k++) {
            float p[4], v[4];
            #pragma unroll
            for (int i = 0; i < 4; i++) p[i] = S[(ty * 4 + i) * 65 + k];
            *(float4*)v = *(const float4*)&KVs[k * 64 + tx * 4];
            #pragma unroll
            for (int i = 0; i < 4; i++)
                #pragma unroll
                for (int j = 0; j < 4; j++)
                    O[i][j] = fmaf(p[i], v[j], O[i][j]);
        }
    }

    if (tid < 64) linv[tid] = 1.f / l;
    __syncthreads();

    #pragma unroll
    for (int i = 0; i < 4; i++) {
        const int r = ty * 4 + i;
        const float inv = linv[r];
        float* op = Hout + (size_t)(b * SEQ + q0 + r) * EMB + h * HD + tx * 4;
        float out[4];
        #pragma unroll
        for (int j = 0; j < 4; j++) out[j] = O[i][j] * inv;
        *(float4*)op = *(float4*)out;
    }
}

// ================= residual add + layernorm =================
__global__ __launch_bounds__(256) void ln_kernel(
    const float* __restrict__ x, const float* __restrict__ hres,
    const float* __restrict__ g, const float* __restrict__ be,
    float* __restrict__ out)
{
    __shared__ float buf[EMB];
    __shared__ float red[8];
    const int row = blockIdx.x;
    const int tid = threadIdx.x;
    const float* xr = x + (size_t)row * EMB;
    const float* hr = hres + (size_t)row * EMB;

    float s = 0.f;
    for (int e = tid; e < EMB; e += 256) {
        float v = xr[e] + hr[e];
        buf[e] = v;
        s += v;
    }
    #pragma unroll
    for (int o = 16; o; o >>= 1) s += __shfl_down_sync(0xffffffffu, s, o);
    if ((tid & 31) == 0) red[tid >> 5] = s;
    __syncthreads();
    if (tid < 8) {
        s = red[tid];
        #pragma unroll
        for (int o = 4; o; o >>= 1) s += __shfl_down_sync(0xffu, s, o);
        if (tid == 0) red[0] = s;
    }
    __syncthreads();
    const float mu = red[0] * (1.f / EMB);
    __syncthreads();

    float vs = 0.f;
    for (int e = tid; e < EMB; e += 256) {
        float d = buf[e] - mu;
        vs += d * d;
    }
    #pragma unroll
    for (int o = 16; o; o >>= 1) vs += __shfl_down_sync(0xffffffffu, vs, o);
    if ((tid & 31) == 0) red[tid >> 5] = vs;
    __syncthreads();
    if (tid < 8) {
        vs = red[tid];
        #pragma unroll
        for (int o = 4; o; o >>= 1) vs += __shfl_down_sync(0xffu, vs, o);
        if (tid == 0) red[0] = vs;
    }
    __syncthreads();
    const float rstd = rsqrtf(red[0] * (1.f / EMB) + LN_EPS);

    for (int e = tid; e < EMB; e += 256)
        out[(size_t)row * EMB + e] = (buf[e] - mu) * rstd * g[e] + be[e];
}

// ================= launch =================
extern "C" void kernel_launch(void* const* d_in, const int* in_sizes, int n_in,
                              void* d_out, int out_size)
{
    const float* x     = (const float*)d_in[0];
    const float* W_qkv = (const float*)d_in[1];
    const float* b_qkv = (const float*)d_in[2];
    const float* W_out = (const float*)d_in[3];
    const float* b_out = (const float*)d_in[4];
    const float* g1    = (const float*)d_in[5];
    const float* be1   = (const float*)d_in[6];
    const float* W_ff1 = (const float*)d_in[7];
    const float* b_ff1 = (const float*)d_in[8];
    const float* W_ff2 = (const float*)d_in[9];
    const float* b_ff2 = (const float*)d_in[10];
    const float* g2    = (const float*)d_in[11];
    const float* be2   = (const float*)d_in[12];
    float* out = (float*)d_out;

    float *qkv, *attn, *tmp, *x1, *ffh;
    cudaGetSymbolAddress((void**)&qkv,  g_qkv);
    cudaGetSymbolAddress((void**)&attn, g_attn);
    cudaGetSymbolAddress((void**)&tmp,  g_tmp);
    cudaGetSymbolAddress((void**)&x1,   g_x1);
    cudaGetSymbolAddress((void**)&ffh,  g_ffh);
    __nv_bfloat16 *qh, *ql, *oh, *ol, *f1h, *f1l, *f2h, *f2l;
    cudaGetSymbolAddress((void**)&qh,  wt_qkv_h);
    cudaGetSymbolAddress((void**)&ql,  wt_qkv_l);
    cudaGetSymbolAddress((void**)&oh,  wt_out_h);
    cudaGetSymbolAddress((void**)&ol,  wt_out_l);
    cudaGetSymbolAddress((void**)&f1h, wt_ff1_h);
    cudaGetSymbolAddress((void**)&f1l, wt_ff1_l);
    cudaGetSymbolAddress((void**)&f2h, wt_ff2_h);
    cudaGetSymbolAddress((void**)&f2l, wt_ff2_l);

    const int attn_smem = (4096 + 4096 + 64 * 65 + 64 + 64) * (int)sizeof(float);
    cudaFuncSetAttribute(attn_kernel, cudaFuncAttributeMaxDynamicSharedMemorySize, attn_smem);
    cudaFuncSetAttribute(gemm_mma, cudaFuncAttributeMaxDynamicSharedMemorySize, GEMM_SMEM);

    // 0) weight transpose + bf16 split (W[K,N] -> T[N,K] hi/lo)
    wconv_kernel<<<dim3(3 * EMB / 32, EMB / 32), dim3(32, 8)>>>(W_qkv, qh, ql, EMB, 3 * EMB);
    wconv_kernel<<<dim3(EMB / 32, EMB / 32),     dim3(32, 8)>>>(W_out, oh, ol, EMB, EMB);
    wconv_kernel<<<dim3(FF_DIM / 32, EMB / 32),  dim3(32, 8)>>>(W_ff1, f1h, f1l, EMB, FF_DIM);
    wconv_kernel<<<dim3(EMB / 32, FF_DIM / 32),  dim3(32, 8)>>>(W_ff2, f2h, f2l, FF_DIM, EMB);

    // 1) qkv = x @ W_qkv + b_qkv
    gemm_mma<<<dim3(3 * EMB / 128, MROWS / 128), 256, GEMM_SMEM>>>(
        x, qh, ql, b_qkv, qkv, MROWS, 3 * EMB, EMB, 0);

    // 2) causal attention
    attn_kernel<<<dim3(SEQ / 64, NH, BATCH), 256, attn_smem>>>(qkv, attn);

    // 3) proj = attn @ W_out + b_out
    gemm_mma<<<dim3(EMB / 128, MROWS / 128), 256, GEMM_SMEM>>>(
        attn, oh, ol, b_out, tmp, MROWS, EMB, EMB, 0);

    // 4) x1 = LN(x + proj)
    ln_kernel<<<MROWS, 256>>>(x, tmp, g1, be1, x1);

    // 5) ffh = relu(x1 @ W_ff1 + b_ff1)
    gemm_mma<<<dim3(FF_DIM / 128, MROWS / 128), 256, GEMM_SMEM>>>(
        x1, f1h, f1l, b_ff1, ffh, MROWS, FF_DIM, EMB, 1);

    // 6) ff = ffh @ W_ff2 + b_ff2
    gemm_mma<<<dim3(EMB / 128, MROWS / 128), 256, GEMM_SMEM>>>(
        ffh, f2h, f2l, b_ff2, tmp, MROWS, EMB, FF_DIM, 0);

    // 7) out = LN(x1 + ff)
    ln_kernel<<<MROWS, 256>>>(x1, tmp, g2, be2, out);
}

// round 5
// speedup vs baseline: 3.2155x; 1.9124x over previous
#include <cuda_runtime.h>
#include <cuda_bf16.h>
#include <cuda_fp16.h>
#include <math.h>
#include <stdint.h>

#define EMB 1024
#define SEQ 2048
#define BATCH 2
#define NH 16
#define HD 64
#define FF_DIM 2048
#define MROWS (BATCH * SEQ)   // 4096
#define LN_EPS 1e-5f

// ================= helpers (baseline PTX ISA only: sm_80-era) =================
__device__ __forceinline__ uint32_t smem_u32(const void* p) {
    uint32_t a;
    asm("{ .reg .u64 t; cvta.to.shared.u64 t, %1; cvt.u32.u64 %0, t; }" : "=r"(a) : "l"(p));
    return a;
}
__device__ __forceinline__ uint32_t sw128(uint32_t off) { return off ^ ((off >> 3) & 0x70); }
__device__ __forceinline__ uint32_t pack_bf16(float a, float b) {
    __nv_bfloat162 t = __floats2bfloat162_rn(a, b);
    return *(uint32_t*)&t;
}
__device__ __forceinline__ uint32_t pack_f16(float a, float b) {
    __half2 t = __floats2half2_rn(a, b);
    return *(uint32_t*)&t;
}

#define CP16(dst, src) asm volatile("cp.async.cg.shared.global [%0], [%1], 16;" :: "r"(dst), "l"(src) : "memory")
#define CP_COMMIT()    asm volatile("cp.async.commit_group;" ::: "memory")
#define CP_WAIT0()     asm volatile("cp.async.wait_group 0;" ::: "memory")

#define LDSM4(r, addr) \
    asm volatile("ldmatrix.sync.aligned.m8n8.x4.shared.b16 {%0,%1,%2,%3}, [%4];" \
        : "=r"((r)[0]), "=r"((r)[1]), "=r"((r)[2]), "=r"((r)[3]) : "r"(addr))
#define LDSM4T(r, addr) \
    asm volatile("ldmatrix.sync.aligned.m8n8.x4.trans.shared.b16 {%0,%1,%2,%3}, [%4];" \
        : "=r"((r)[0]), "=r"((r)[1]), "=r"((r)[2]), "=r"((r)[3]) : "r"(addr))

#define MMA16816(d, a, b0, b1) \
    asm volatile("mma.sync.aligned.m16n8k16.row.col.f32.bf16.bf16.f32 " \
        "{%0,%1,%2,%3},{%4,%5,%6,%7},{%8,%9},{%0,%1,%2,%3};" \
        : "+f"((d)[0]), "+f"((d)[1]), "+f"((d)[2]), "+f"((d)[3]) \
        : "r"((a)[0]), "r"((a)[1]), "r"((a)[2]), "r"((a)[3]), "r"(b0), "r"(b1))
#define MMAF16(d, a, b0, b1) \
    asm volatile("mma.sync.aligned.m16n8k16.row.col.f32.f16.f16.f32 " \
        "{%0,%1,%2,%3},{%4,%5,%6,%7},{%8,%9},{%0,%1,%2,%3};" \
        : "+f"((d)[0]), "+f"((d)[1]), "+f"((d)[2]), "+f"((d)[3]) \
        : "r"((a)[0]), "r"((a)[1]), "r"((a)[2]), "r"((a)[3]), "r"(b0), "r"(b1))

// ================= scratch =================
__device__ float g_qkv[(size_t)MROWS * 3 * EMB];
__device__ float g_attn[(size_t)MROWS * EMB];
__device__ float g_tmp[(size_t)MROWS * EMB];
__device__ float g_x1[(size_t)MROWS * EMB];
__device__ float g_ffh[(size_t)MROWS * FF_DIM];
__device__ __nv_bfloat16 wt_qkv_h[(size_t)3 * EMB * EMB], wt_qkv_l[(size_t)3 * EMB * EMB];
__device__ __nv_bfloat16 wt_out_h[(size_t)EMB * EMB],     wt_out_l[(size_t)EMB * EMB];
__device__ __nv_bfloat16 wt_ff1_h[(size_t)FF_DIM * EMB],  wt_ff1_l[(size_t)FF_DIM * EMB];
__device__ __nv_bfloat16 wt_ff2_h[(size_t)EMB * FF_DIM],  wt_ff2_l[(size_t)EMB * FF_DIM];

// ============ weight transpose + bf16 hi/lo split: W[K,N] -> T[N,K] ============
__global__ __launch_bounds__(256) void wconv_kernel(
    const float* __restrict__ W, __nv_bfloat16* __restrict__ Th,
    __nv_bfloat16* __restrict__ Tl, int K, int N)
{
    __shared__ float sm[32][33];
    const int tx = threadIdx.x, ty = threadIdx.y;
    const int n0 = blockIdx.x * 32, k0 = blockIdx.y * 32;
    #pragma unroll
    for (int i = 0; i < 4; i++)
        sm[ty + i * 8][tx] = W[(size_t)(k0 + ty + i * 8) * N + n0 + tx];
    __syncthreads();
    #pragma unroll
    for (int i = 0; i < 4; i++) {
        int nl = ty + i * 8;
        float v = sm[tx][nl];
        __nv_bfloat16 h = __float2bfloat16_rn(v);
        __nv_bfloat16 l = __float2bfloat16_rn(v - __bfloat162float(h));
        size_t o = (size_t)(n0 + nl) * K + k0 + tx;
        Th[o] = h;
        Tl[o] = l;
    }
}

// ============ bf16-split HMMA GEMM (unchanged from R4) ============
#define ST_BYTES 65536
#define OFF_AH 0
#define OFF_AL 16384
#define OFF_BH 32768
#define OFF_BL 49152
#define GEMM_SMEM (2 * ST_BYTES)

__device__ __forceinline__ void gemm_ldA(
    float4 (&r)[8], const float* __restrict__ A, int K, int m0, int kc, int tid)
{
    #pragma unroll
    for (int it = 0; it < 8; it++) {
        int idx = it * 256 + tid;
        int row = idx >> 4, c4 = idx & 15;
        r[it] = *(const float4*)(A + (size_t)(m0 + row) * K + kc + c4 * 4);
    }
}
__device__ __forceinline__ void gemm_stsA(
    const float4 (&r)[8], char* smst, int tid)
{
    #pragma unroll
    for (int it = 0; it < 8; it++) {
        int idx = it * 256 + tid;
        int row = idx >> 4, c4 = idx & 15;
        uint32_t sw = sw128((uint32_t)(row * 128 + c4 * 8));
        float4 v = r[it];
        __nv_bfloat16 h0 = __float2bfloat16_rn(v.x), h1 = __float2bfloat16_rn(v.y);
        __nv_bfloat16 h2 = __float2bfloat16_rn(v.z), h3 = __float2bfloat16_rn(v.w);
        __nv_bfloat162 p0; p0.x = h0; p0.y = h1;
        __nv_bfloat162 p1; p1.x = h2; p1.y = h3;
        uint2 hh = make_uint2(*(uint32_t*)&p0, *(uint32_t*)&p1);
        uint2 ll = make_uint2(
            pack_bf16(v.x - __bfloat162float(h0), v.y - __bfloat162float(h1)),
            pack_bf16(v.z - __bfloat162float(h2), v.w - __bfloat162float(h3)));
        *(uint2*)(smst + OFF_AH + sw) = hh;
        *(uint2*)(smst + OFF_AL + sw) = ll;
    }
}
__device__ __forceinline__ void gemm_cpB(
    const __nv_bfloat16* __restrict__ Bh, const __nv_bfloat16* __restrict__ Bl,
    uint32_t sdst, int K, int n0, int kc, int tid)
{
    #pragma unroll
    for (int it = 0; it < 4; it++) {
        int idx = it * 256 + tid;
        int row = idx >> 3, ch = idx & 7;
        uint32_t sw = sw128((uint32_t)(row * 128 + ch * 16));
        const __nv_bfloat16* gh = Bh + (size_t)(n0 + row) * K + kc + ch * 8;
        const __nv_bfloat16* gl = Bl + (size_t)(n0 + row) * K + kc + ch * 8;
        CP16(sdst + OFF_BH + sw, gh);
        CP16(sdst + OFF_BL + sw, gl);
    }
    CP_COMMIT();
}

__global__ __launch_bounds__(256, 1) void gemm_mma(
    const float* __restrict__ A, const __nv_bfloat16* __restrict__ Bh,
    const __nv_bfloat16* __restrict__ Bl, const float* __restrict__ bias,
    float* __restrict__ C, int M, int N, int K, int relu)
{
    extern __shared__ char sm[];
    const uint32_t smb = smem_u32(sm);
    const int tid = threadIdx.x;
    const int wid = tid >> 5, lane = tid & 31;
    const int m0 = blockIdx.y * 128, n0 = blockIdx.x * 128;
    const int wm = (wid & 3) * 32, wn = (wid >> 2) * 64;
    const int NC = K >> 6;

    float acc[2][8][4];
    #pragma unroll
    for (int i = 0; i < 2; i++)
        #pragma unroll
        for (int j = 0; j < 8; j++)
            #pragma unroll
            for (int q = 0; q < 4; q++) acc[i][j][q] = 0.f;

    float4 ra[8];
    gemm_cpB(Bh, Bl, smb, K, n0, 0, tid);
    gemm_ldA(ra, A, K, m0, 0, tid);
    gemm_stsA(ra, sm, tid);
    CP_WAIT0();
    __syncthreads();

    for (int c = 0; c < NC; c++) {
        const int cur = c & 1;
        const bool more = (c + 1 < NC);
        if (more) {
            gemm_cpB(Bh, Bl, smb + (cur ^ 1) * ST_BYTES, K, n0, (c + 1) << 6, tid);
            gemm_ldA(ra, A, K, m0, (c + 1) << 6, tid);
        }
        const uint32_t s0 = smb + cur * ST_BYTES;
        #pragma unroll
        for (int kk = 0; kk < 4; kk++) {
            uint32_t ah[2][4], al[2][4];
            #pragma unroll
            for (int mt = 0; mt < 2; mt++) {
                int row = wm + mt * 16 + (lane & 15);
                uint32_t cbhi = (uint32_t)(kk * 2 + (lane >> 4));
                uint32_t off = (uint32_t)(row * 128) + ((cbhi ^ (row & 7)) << 4);
                LDSM4(ah[mt], s0 + OFF_AH + off);
                LDSM4(al[mt], s0 + OFF_AL + off);
            }
            #pragma unroll
            for (int g = 0; g < 4; g++) {
                int nrow = wn + g * 16 + ((lane >> 4) << 3) + (lane & 7);
                uint32_t cbhi = (uint32_t)(kk * 2 + ((lane >> 3) & 1));
                uint32_t off = (uint32_t)(nrow * 128) + ((cbhi ^ (nrow & 7)) << 4);
                uint32_t bh[4], bl[4];
                LDSM4(bh, s0 + OFF_BH + off);
                LDSM4(bl, s0 + OFF_BL + off);
                #pragma unroll
                for (int mt = 0; mt < 2; mt++) {
                    MMA16816(acc[mt][2 * g],     ah[mt], bh[0], bh[1]);
                    MMA16816(acc[mt][2 * g + 1], ah[mt], bh[2], bh[3]);
                    MMA16816(acc[mt][2 * g],     ah[mt], bl[0], bl[1]);
                    MMA16816(acc[mt][2 * g + 1], ah[mt], bl[2], bl[3]);
                    MMA16816(acc[mt][2 * g],     al[mt], bh[0], bh[1]);
                    MMA16816(acc[mt][2 * g + 1], al[mt], bh[2], bh[3]);
                }
            }
        }
        __syncthreads();
        if (more) {
            gemm_stsA(ra, sm + (cur ^ 1) * ST_BYTES, tid);
            CP_WAIT0();
            __syncthreads();
        }
    }

    #pragma unroll
    for (int mt = 0; mt < 2; mt++) {
        #pragma unroll
        for (int nt = 0; nt < 8; nt++) {
            int r0 = m0 + wm + mt * 16 + (lane >> 2);
            int col = n0 + wn + nt * 8 + (lane & 3) * 2;
            float2 bb = *(const float2*)(bias + col);
            float v0 = acc[mt][nt][0] + bb.x;
            float v1 = acc[mt][nt][1] + bb.y;
            float v2 = acc[mt][nt][2] + bb.x;
            float v3 = acc[mt][nt][3] + bb.y;
            if (relu) {
                v0 = fmaxf(v0, 0.f); v1 = fmaxf(v1, 0.f);
                v2 = fmaxf(v2, 0.f); v3 = fmaxf(v3, 0.f);
            }
            float2 o0 = make_float2(v0, v1), o1 = make_float2(v2, v3);
            *(float2*)(C + (size_t)r0 * N + col) = o0;
            *(float2*)(C + (size_t)(r0 + 8) * N + col) = o1;
        }
    }
}

// ================= flash attention v2: fp16 HMMA, register softmax =================
// CTA: 128 q rows of one (b,h). 8 warps x 16 rows. kv tiles of 64.
// smem: Q fp16 [128][64] @0 (16KB) | K fp16 [64][64] @16K (8KB) | V fp16 [64][64] @24K (8KB)
__global__ __launch_bounds__(256) void attn_mma(
    const float* __restrict__ qkv, float* __restrict__ Hout)
{
    __shared__ char sma[32768];
    const uint32_t sb = smem_u32(sma);
    const uint32_t sQ = sb, sK = sb + 16384, sV = sb + 24576;

    const int tid = threadIdx.x, lane = tid & 31, w = tid >> 5;
    const int qb = blockIdx.x, h = blockIdx.y, b = blockIdx.z;
    const int q0 = qb * 128;
    const float* base = qkv + (size_t)b * SEQ * 3 * EMB;

    // ---- load Q tile (scaled by 1/8), fp32 -> fp16 swizzled smem ----
    #pragma unroll
    for (int it = 0; it < 8; it++) {
        int idx = it * 256 + tid;
        int row = idx >> 4, c4 = idx & 15;
        float4 v = *(const float4*)(base + (size_t)(q0 + row) * (3 * EMB) + h * HD + c4 * 4);
        uint32_t off = sw128((uint32_t)(row * 128 + c4 * 8));
        *(uint2*)(sma + off) = make_uint2(pack_f16(v.x * 0.125f, v.y * 0.125f),
                                          pack_f16(v.z * 0.125f, v.w * 0.125f));
    }
    __syncthreads();

    // ---- hoist Q fragments (A operand), 4 k16 chunks ----
    uint32_t qf[4][4];
    #pragma unroll
    for (int kk = 0; kk < 4; kk++) {
        int row = w * 16 + (lane & 15);
        uint32_t cbhi = (uint32_t)(kk * 2 + (lane >> 4));
        uint32_t off = (uint32_t)(row * 128) + ((cbhi ^ (row & 7)) << 4);
        LDSM4(qf[kk], sQ + off);
    }

    float o[8][4];
    #pragma unroll
    for (int i = 0; i < 8; i++)
        #pragma unroll
        for (int j = 0; j < 4; j++) o[i][j] = 0.f;
    float m0 = -INFINITY, m1 = -INFINITY, l0 = 0.f, l1 = 0.f;

    const int rbase = q0 + w * 16 + (lane >> 2);
    const int rmin = q0 + w * 16;
    const int nkv = (q0 >> 6) + 2;

    for (int t = 0; t < nkv; t++) {
        const int k0t = t * 64;
        __syncthreads();
        // load K, V tiles fp32 -> fp16 swizzled
        #pragma unroll
        for (int it = 0; it < 4; it++) {
            int idx = it * 256 + tid;
            int row = idx >> 4, c4 = idx & 15;
            const float* gk = base + (size_t)(k0t + row) * (3 * EMB) + EMB + h * HD + c4 * 4;
            float4 kv4 = *(const float4*)gk;
            float4 vv4 = *(const float4*)(gk + EMB);
            uint32_t off = sw128((uint32_t)(row * 128 + c4 * 8));
            *(uint2*)(sma + 16384 + off) = make_uint2(pack_f16(kv4.x, kv4.y), pack_f16(kv4.z, kv4.w));
            *(uint2*)(sma + 24576 + off) = make_uint2(pack_f16(vv4.x, vv4.y), pack_f16(vv4.z, vv4.w));
        }
        __syncthreads();

        // ---- S = Q K^T ----
        float s[8][4];
        #pragma unroll
        for (int i = 0; i < 8; i++)
            #pragma unroll
            for (int j = 0; j < 4; j++) s[i][j] = 0.f;
        #pragma unroll
        for (int kk = 0; kk < 4; kk++) {
            #pragma unroll
            for (int g = 0; g < 4; g++) {
                int nrow = g * 16 + ((lane >> 4) << 3) + (lane & 7);
                uint32_t cbhi = (uint32_t)(kk * 2 + ((lane >> 3) & 1));
                uint32_t off = (uint32_t)(nrow * 128) + ((cbhi ^ (nrow & 7)) << 4);
                uint32_t kf[4];
                LDSM4(kf, sK + off);
                MMAF16(s[2 * g],     qf[kk], kf[0], kf[1]);
                MMAF16(s[2 * g + 1], qf[kk], kf[2], kf[3]);
            }
        }

        // ---- causal mask (only when tile crosses the warp's diagonal) ----
        if (k0t + 63 > rmin) {
            #pragma unroll
            for (int nf = 0; nf < 8; nf++) {
                int colb = k0t + nf * 8 + ((lane & 3) << 1);
                if (colb > rbase)     s[nf][0] = -INFINITY;
                if (colb + 1 > rbase) s[nf][1] = -INFINITY;
                if (colb > rbase + 8)     s[nf][2] = -INFINITY;
                if (colb + 1 > rbase + 8) s[nf][3] = -INFINITY;
            }
        }

        // ---- online softmax in registers ----
        float mx0 = -INFINITY, mx1 = -INFINITY;
        #pragma unroll
        for (int nf = 0; nf < 8; nf++) {
            mx0 = fmaxf(mx0, fmaxf(s[nf][0], s[nf][1]));
            mx1 = fmaxf(mx1, fmaxf(s[nf][2], s[nf][3]));
        }
        mx0 = fmaxf(mx0, __shfl_xor_sync(0xffffffffu, mx0, 1));
        mx0 = fmaxf(mx0, __shfl_xor_sync(0xffffffffu, mx0, 2));
        mx1 = fmaxf(mx1, __shfl_xor_sync(0xffffffffu, mx1, 1));
        mx1 = fmaxf(mx1, __shfl_xor_sync(0xffffffffu, mx1, 2));
        const float mn0 = fmaxf(m0, mx0), mn1 = fmaxf(m1, mx1);
        const float c0 = __expf(m0 - mn0), c1 = __expf(m1 - mn1);
        float sum0 = 0.f, sum1 = 0.f;
        #pragma unroll
        for (int nf = 0; nf < 8; nf++) {
            s[nf][0] = __expf(s[nf][0] - mn0);
            s[nf][1] = __expf(s[nf][1] - mn0);
            s[nf][2] = __expf(s[nf][2] - mn1);
            s[nf][3] = __expf(s[nf][3] - mn1);
            sum0 += s[nf][0] + s[nf][1];
            sum1 += s[nf][2] + s[nf][3];
        }
        sum0 += __shfl_xor_sync(0xffffffffu, sum0, 1);
        sum0 += __shfl_xor_sync(0xffffffffu, sum0, 2);
        sum1 += __shfl_xor_sync(0xffffffffu, sum1, 1);
        sum1 += __shfl_xor_sync(0xffffffffu, sum1, 2);
        l0 = l0 * c0 + sum0;
        l1 = l1 * c1 + sum1;
        m0 = mn0;
        m1 = mn1;
        #pragma unroll
        for (int nf = 0; nf < 8; nf++) {
            o[nf][0] *= c0; o[nf][1] *= c0;
            o[nf][2] *= c1; o[nf][3] *= c1;
        }

        // ---- O += P V : P accum frags -> fp16 A frags, V via ldmatrix.trans ----
        #pragma unroll
        for (int kk = 0; kk < 4; kk++) {
            uint32_t pf[4];
            pf[0] = pack_f16(s[2 * kk][0],     s[2 * kk][1]);
            pf[1] = pack_f16(s[2 * kk][2],     s[2 * kk][3]);
            pf[2] = pack_f16(s[2 * kk + 1][0], s[2 * kk + 1][1]);
            pf[3] = pack_f16(s[2 * kk + 1][2], s[2 * kk + 1][3]);
            #pragma unroll
            for (int dg = 0; dg < 4; dg++) {
                int row = kk * 16 + (((lane >> 3) & 1) << 3) + (lane & 7);
                int cole = dg * 16 + ((lane >> 4) << 3);
                uint32_t off = sw128((uint32_t)(row * 128 + cole * 2));
                uint32_t vf[4];
                LDSM4T(vf, sV + off);
                MMAF16(o[2 * dg],     pf, vf[0], vf[1]);
                MMAF16(o[2 * dg + 1], pf, vf[2], vf[3]);
            }
        }
    }

    // ---- epilogue: normalize + store to head-concat layout ----
    const float li0 = 1.f / l0, li1 = 1.f / l1;
    const int row0 = q0 + w * 16 + (lane >> 2);
    #pragma unroll
    for (int nf = 0; nf < 8; nf++) {
        int col = h * HD + nf * 8 + ((lane & 3) << 1);
        float* p0 = Hout + (size_t)(b * SEQ + row0) * EMB + col;
        float* p1 = Hout + (size_t)(b * SEQ + row0 + 8) * EMB + col;
        *(float2*)p0 = make_float2(o[nf][0] * li0, o[nf][1] * li0);
        *(float2*)p1 = make_float2(o[nf][2] * li1, o[nf][3] * li1);
    }
}

// ================= residual add + layernorm =================
__global__ __launch_bounds__(256) void ln_kernel(
    const float* __restrict__ x, const float* __restrict__ hres,
    const float* __restrict__ g, const float* __restrict__ be,
    float* __restrict__ out)
{
    __shared__ float buf[EMB];
    __shared__ float red[8];
    const int row = blockIdx.x;
    const int tid = threadIdx.x;
    const float* xr = x + (size_t)row * EMB;
    const float* hr = hres + (size_t)row * EMB;

    float s = 0.f;
    for (int e = tid; e < EMB; e += 256) {
        float v = xr[e] + hr[e];
        buf[e] = v;
        s += v;
    }
    #pragma unroll
    for (int o = 16; o; o >>= 1) s += __shfl_down_sync(0xffffffffu, s, o);
    if ((tid & 31) == 0) red[tid >> 5] = s;
    __syncthreads();
    if (tid < 8) {
        s = red[tid];
        #pragma unroll
        for (int o = 4; o; o >>= 1) s += __shfl_down_sync(0xffu, s, o);
        if (tid == 0) red[0] = s;
    }
    __syncthreads();
    const float mu = red[0] * (1.f / EMB);
    __syncthreads();

    float vs = 0.f;
    for (int e = tid; e < EMB; e += 256) {
        float d = buf[e] - mu;
        vs += d * d;
    }
    #pragma unroll
    for (int o = 16; o; o >>= 1) vs += __shfl_down_sync(0xffffffffu, vs, o);
    if ((tid & 31) == 0) red[tid >> 5] = vs;
    __syncthreads();
    if (tid < 8) {
        vs = red[tid];
        #pragma unroll
        for (int o = 4; o; o >>= 1) vs += __shfl_down_sync(0xffu, vs, o);
        if (tid == 0) red[0] = vs;
    }
    __syncthreads();
    const float rstd = rsqrtf(red[0] * (1.f / EMB) + LN_EPS);

    for (int e = tid; e < EMB; e += 256)
        out[(size_t)row * EMB + e] = (buf[e] - mu) * rstd * g[e] + be[e];
}

// ================= launch =================
extern "C" void kernel_launch(void* const* d_in, const int* in_sizes, int n_in,
                              void* d_out, int out_size)
{
    const float* x     = (const float*)d_in[0];
    const float* W_qkv = (const float*)d_in[1];
    const float* b_qkv = (const float*)d_in[2];
    const float* W_out = (const float*)d_in[3];
    const float* b_out = (const float*)d_in[4];
    const float* g1    = (const float*)d_in[5];
    const float* be1   = (const float*)d_in[6];
    const float* W_ff1 = (const float*)d_in[7];
    const float* b_ff1 = (const float*)d_in[8];
    const float* W_ff2 = (const float*)d_in[9];
    const float* b_ff2 = (const float*)d_in[10];
    const float* g2    = (const float*)d_in[11];
    const float* be2   = (const float*)d_in[12];
    float* out = (float*)d_out;

    float *qkv, *attn, *tmp, *x1, *ffh;
    cudaGetSymbolAddress((void**)&qkv,  g_qkv);
    cudaGetSymbolAddress((void**)&attn, g_attn);
    cudaGetSymbolAddress((void**)&tmp,  g_tmp);
    cudaGetSymbolAddress((void**)&x1,   g_x1);
    cudaGetSymbolAddress((void**)&ffh,  g_ffh);
    __nv_bfloat16 *qh, *ql, *oh, *ol, *f1h, *f1l, *f2h, *f2l;
    cudaGetSymbolAddress((void**)&qh,  wt_qkv_h);
    cudaGetSymbolAddress((void**)&ql,  wt_qkv_l);
    cudaGetSymbolAddress((void**)&oh,  wt_out_h);
    cudaGetSymbolAddress((void**)&ol,  wt_out_l);
    cudaGetSymbolAddress((void**)&f1h, wt_ff1_h);
    cudaGetSymbolAddress((void**)&f1l, wt_ff1_l);
    cudaGetSymbolAddress((void**)&f2h, wt_ff2_h);
    cudaGetSymbolAddress((void**)&f2l, wt_ff2_l);

    cudaFuncSetAttribute(gemm_mma, cudaFuncAttributeMaxDynamicSharedMemorySize, GEMM_SMEM);

    // 0) weight transpose + bf16 split
    wconv_kernel<<<dim3(3 * EMB / 32, EMB / 32), dim3(32, 8)>>>(W_qkv, qh, ql, EMB, 3 * EMB);
    wconv_kernel<<<dim3(EMB / 32, EMB / 32),     dim3(32, 8)>>>(W_out, oh, ol, EMB, EMB);
    wconv_kernel<<<dim3(FF_DIM / 32, EMB / 32),  dim3(32, 8)>>>(W_ff1, f1h, f1l, EMB, FF_DIM);
    wconv_kernel<<<dim3(EMB / 32, FF_DIM / 32),  dim3(32, 8)>>>(W_ff2, f2h, f2l, FF_DIM, EMB);

    // 1) qkv = x @ W_qkv + b_qkv
    gemm_mma<<<dim3(3 * EMB / 128, MROWS / 128), 256, GEMM_SMEM>>>(
        x, qh, ql, b_qkv, qkv, MROWS, 3 * EMB, EMB, 0);

    // 2) causal attention (fp16 HMMA flash)
    attn_mma<<<dim3(SEQ / 128, NH, BATCH), 256>>>(qkv, attn);

    // 3) proj = attn @ W_out + b_out
    gemm_mma<<<dim3(EMB / 128, MROWS / 128), 256, GEMM_SMEM>>>(
        attn, oh, ol, b_out, tmp, MROWS, EMB, EMB, 0);

    // 4) x1 = LN(x + proj)
    ln_kernel<<<MROWS, 256>>>(x, tmp, g1, be1, x1);

    // 5) ffh = relu(x1 @ W_ff1 + b_ff1)
    gemm_mma<<<dim3(FF_DIM / 128, MROWS / 128), 256, GEMM_SMEM>>>(
        x1, f1h, f1l, b_ff1, ffh, MROWS, FF_DIM, EMB, 1);

    // 6) ff = ffh @ W_ff2 + b_ff2
    gemm_mma<<<dim3(EMB / 128, MROWS / 128), 256, GEMM_SMEM>>>(
        ffh, f2h, f2l, b_ff2, tmp, MROWS, EMB, FF_DIM, 0);

    // 7) out = LN(x1 + ff)
    ln_kernel<<<MROWS, 256>>>(x1, tmp, g2, be2, out);
}

// round 6
// speedup vs baseline: 7.5995x; 2.3634x over previous
#include <cuda_runtime.h>
#include <cuda_fp16.h>
#include <math.h>
#include <stdint.h>

#define EMB 1024
#define SEQ 2048
#define BATCH 2
#define NH 16
#define HD 64
#define FF_DIM 2048
#define MROWS (BATCH * SEQ)   // 4096
#define LN_EPS 1e-5f

// ================= helpers (baseline PTX ISA, sm_80-era) =================
__device__ __forceinline__ uint32_t smem_u32(const void* p) {
    uint32_t a;
    asm("{ .reg .u64 t; cvta.to.shared.u64 t, %1; cvt.u32.u64 %0, t; }" : "=r"(a) : "l"(p));
    return a;
}
__device__ __forceinline__ uint32_t sw128(uint32_t off) { return off ^ ((off >> 3) & 0x70); }

#define CP16(dst, src) asm volatile("cp.async.cg.shared.global [%0], [%1], 16;" :: "r"(dst), "l"(src) : "memory")
#define CP_COMMIT()    asm volatile("cp.async.commit_group;" ::: "memory")
#define CP_WAIT0()     asm volatile("cp.async.wait_group 0;" ::: "memory")

#define LDSM4(r, addr) \
    asm volatile("ldmatrix.sync.aligned.m8n8.x4.shared.b16 {%0,%1,%2,%3}, [%4];" \
        : "=r"((r)[0]), "=r"((r)[1]), "=r"((r)[2]), "=r"((r)[3]) : "r"(addr))
#define LDSM4T(r, addr) \
    asm volatile("ldmatrix.sync.aligned.m8n8.x4.trans.shared.b16 {%0,%1,%2,%3}, [%4];" \
        : "=r"((r)[0]), "=r"((r)[1]), "=r"((r)[2]), "=r"((r)[3]) : "r"(addr))

#define MMAF16(d, a, b0, b1) \
    asm volatile("mma.sync.aligned.m16n8k16.row.col.f32.f16.f16.f32 " \
        "{%0,%1,%2,%3},{%4,%5,%6,%7},{%8,%9},{%0,%1,%2,%3};" \
        : "+f"((d)[0]), "+f"((d)[1]), "+f"((d)[2]), "+f"((d)[3]) \
        : "r"((a)[0]), "r"((a)[1]), "r"((a)[2]), "r"((a)[3]), "r"(b0), "r"(b1))

__device__ __forceinline__ uint32_t pack_f16(float a, float b) {
    __half2 t = __floats2half2_rn(a, b);
    return *(uint32_t*)&t;
}

// ================= scratch =================
__device__ __half g_x16[(size_t)MROWS * EMB];         // fp16 copy of x
__device__ __half g_qkv16[(size_t)MROWS * 3 * EMB];   // qkv (fp16)
__device__ __half g_attn16[(size_t)MROWS * EMB];      // attention out (fp16)
__device__ __half g_x116[(size_t)MROWS * EMB];        // post-LN1 (fp16)
__device__ __half g_ffh16[(size_t)MROWS * FF_DIM];    // relu(ff1) (fp16)
__device__ float  g_tmp[(size_t)MROWS * EMB];         // proj / ff2 out (fp32)
__device__ float  g_x1[(size_t)MROWS * EMB];          // post-LN1 (fp32)
__device__ __half wt_qkv16[(size_t)3 * EMB * EMB];    // weights [N,K] fp16
__device__ __half wt_out16[(size_t)EMB * EMB];
__device__ __half wt_ff116[(size_t)FF_DIM * EMB];
__device__ __half wt_ff216[(size_t)EMB * FF_DIM];

// ============ weight transpose fp32[K,N] -> fp16[N,K] ============
__global__ __launch_bounds__(256) void wconv_kernel(
    const float* __restrict__ W, __half* __restrict__ T, int K, int N)
{
    __shared__ float sm[32][33];
    const int tx = threadIdx.x, ty = threadIdx.y;
    const int n0 = blockIdx.x * 32, k0 = blockIdx.y * 32;
    #pragma unroll
    for (int i = 0; i < 4; i++)
        sm[ty + i * 8][tx] = W[(size_t)(k0 + ty + i * 8) * N + n0 + tx];
    __syncthreads();
    #pragma unroll
    for (int i = 0; i < 4; i++) {
        int nl = ty + i * 8;
        T[(size_t)(n0 + nl) * K + k0 + tx] = __float2half(sm[tx][nl]);
    }
}

// ============ x fp32 -> fp16 ============
__global__ __launch_bounds__(256) void xconv_kernel(
    const float* __restrict__ x, __half* __restrict__ x16, int n4)
{
    int i = blockIdx.x * 256 + threadIdx.x;
    if (i < n4) {
        float4 v = *(const float4*)(x + (size_t)i * 4);
        uint2 p = make_uint2(pack_f16(v.x, v.y), pack_f16(v.z, v.w));
        *(uint2*)(x16 + (size_t)i * 4) = p;
    }
}

// ============ fp16 HMMA GEMM: C = A[M,K] @ B[N,K]^T + bias ============
// CTA tile 128x128, BK=64, double-buffered cp.async. 8 warps (4M x 2N), warp 32x64.
#define ST_BYTES 32768
#define OFF_A 0
#define OFF_B 16384
#define GEMM_SMEM (2 * ST_BYTES)

__device__ __forceinline__ void cp_tile16(
    const __half* __restrict__ g, uint32_t sdst, int ldk, int row0, int kc, int tid)
{
    #pragma unroll
    for (int it = 0; it < 4; it++) {
        int idx = it * 256 + tid;
        int row = idx >> 3, ch = idx & 7;
        CP16(sdst + sw128((uint32_t)(row * 128 + ch * 16)),
             g + (size_t)(row0 + row) * ldk + kc + ch * 8);
    }
}

__global__ __launch_bounds__(256, 2) void gemm_f16(
    const __half* __restrict__ A, const __half* __restrict__ B,
    const float* __restrict__ bias, float* __restrict__ C32,
    __half* __restrict__ C16, int M, int N, int K, int relu)
{
    extern __shared__ char sm[];
    const uint32_t smb = smem_u32(sm);
    const int tid = threadIdx.x, wid = tid >> 5, lane = tid & 31;
    const int m0 = blockIdx.y * 128, n0 = blockIdx.x * 128;
    const int wm = (wid & 3) * 32, wn = (wid >> 2) * 64;
    const int NC = K >> 6;

    float acc[2][8][4];
    #pragma unroll
    for (int i = 0; i < 2; i++)
        #pragma unroll
        for (int j = 0; j < 8; j++)
            #pragma unroll
            for (int q = 0; q < 4; q++) acc[i][j][q] = 0.f;

    cp_tile16(A, smb + OFF_A, K, m0, 0, tid);
    cp_tile16(B, smb + OFF_B, K, n0, 0, tid);
    CP_COMMIT();
    CP_WAIT0();
    __syncthreads();

    for (int c = 0; c < NC; c++) {
        const int cur = c & 1;
        const bool more = (c + 1 < NC);
        if (more) {
            const uint32_t st = smb + (cur ^ 1) * ST_BYTES;
            cp_tile16(A, st + OFF_A, K, m0, (c + 1) << 6, tid);
            cp_tile16(B, st + OFF_B, K, n0, (c + 1) << 6, tid);
            CP_COMMIT();
        }
        const uint32_t s0 = smb + cur * ST_BYTES;
        #pragma unroll
        for (int kk = 0; kk < 4; kk++) {
            uint32_t af[2][4];
            #pragma unroll
            for (int mt = 0; mt < 2; mt++) {
                int row = wm + mt * 16 + (lane & 15);
                uint32_t cbhi = (uint32_t)(kk * 2 + (lane >> 4));
                LDSM4(af[mt], s0 + OFF_A + (uint32_t)(row * 128) + ((cbhi ^ (row & 7)) << 4));
            }
            #pragma unroll
            for (int g = 0; g < 4; g++) {
                int nrow = wn + g * 16 + ((lane >> 4) << 3) + (lane & 7);
                uint32_t cbhi = (uint32_t)(kk * 2 + ((lane >> 3) & 1));
                uint32_t bf[4];
                LDSM4(bf, s0 + OFF_B + (uint32_t)(nrow * 128) + ((cbhi ^ (nrow & 7)) << 4));
                #pragma unroll
                for (int mt = 0; mt < 2; mt++) {
                    MMAF16(acc[mt][2 * g],     af[mt], bf[0], bf[1]);
                    MMAF16(acc[mt][2 * g + 1], af[mt], bf[2], bf[3]);
                }
            }
        }
        if (more) {
            CP_WAIT0();
            __syncthreads();
        }
    }

    // epilogue: bias + optional relu; fp32 and/or fp16 outputs
    #pragma unroll
    for (int mt = 0; mt < 2; mt++) {
        #pragma unroll
        for (int nt = 0; nt < 8; nt++) {
            int r0 = m0 + wm + mt * 16 + (lane >> 2);
            int col = n0 + wn + nt * 8 + (lane & 3) * 2;
            float2 bb = *(const float2*)(bias + col);
            float v0 = acc[mt][nt][0] + bb.x;
            float v1 = acc[mt][nt][1] + bb.y;
            float v2 = acc[mt][nt][2] + bb.x;
            float v3 = acc[mt][nt][3] + bb.y;
            if (relu) {
                v0 = fmaxf(v0, 0.f); v1 = fmaxf(v1, 0.f);
                v2 = fmaxf(v2, 0.f); v3 = fmaxf(v3, 0.f);
            }
            if (C32) {
                *(float2*)(C32 + (size_t)r0 * N + col) = make_float2(v0, v1);
                *(float2*)(C32 + (size_t)(r0 + 8) * N + col) = make_float2(v2, v3);
            }
            if (C16) {
                *(uint32_t*)(C16 + (size_t)r0 * N + col) = pack_f16(v0, v1);
                *(uint32_t*)(C16 + (size_t)(r0 + 8) * N + col) = pack_f16(v2, v3);
            }
        }
    }
}

// ================= flash attention: fp16 in/out, double-buffered KV =================
// CTA: 128 q rows of one (b,h). 8 warps x 16 rows. kv tiles of 64.
// smem: Q[128][64] @0 | K0 @16K | K1 @24K | V0 @32K | V1 @40K  (48KB dynamic)
__global__ __launch_bounds__(256, 2) void attn_mma(
    const __half* __restrict__ qkv, __half* __restrict__ Hout)
{
    extern __shared__ char sma[];
    const uint32_t sb = smem_u32(sma);

    const int tid = threadIdx.x, lane = tid & 31, w = tid >> 5;
    const int qb = blockIdx.x, h = blockIdx.y, b = blockIdx.z;
    const int q0 = qb * 128;
    const __half* base = qkv + (size_t)b * SEQ * 3 * EMB;

    // prologue: Q tile + KV tile 0 (buf 0), single cp.async group
    #pragma unroll
    for (int it = 0; it < 4; it++) {
        int idx = it * 256 + tid;
        int row = idx >> 3, ch = idx & 7;
        CP16(sb + sw128((uint32_t)(row * 128 + ch * 16)),
             base + (size_t)(q0 + row) * (3 * EMB) + h * HD + ch * 8);
    }
    #pragma unroll
    for (int it = 0; it < 2; it++) {
        int idx = it * 256 + tid;
        int row = idx >> 3, ch = idx & 7;
        uint32_t soff = sw128((uint32_t)(row * 128 + ch * 16));
        const __half* gk = base + (size_t)row * (3 * EMB) + EMB + h * HD + ch * 8;
        CP16(sb + 16384 + soff, gk);
        CP16(sb + 32768 + soff, gk + EMB);
    }
    CP_COMMIT();
    CP_WAIT0();
    __syncthreads();

    // hoist Q fragments
    uint32_t qf[4][4];
    #pragma unroll
    for (int kk = 0; kk < 4; kk++) {
        int row = w * 16 + (lane & 15);
        uint32_t cbhi = (uint32_t)(kk * 2 + (lane >> 4));
        LDSM4(qf[kk], sb + (uint32_t)(row * 128) + ((cbhi ^ (row & 7)) << 4));
    }

    float o[8][4];
    #pragma unroll
    for (int i = 0; i < 8; i++)
        #pragma unroll
        for (int j = 0; j < 4; j++) o[i][j] = 0.f;
    float m0 = -INFINITY, m1 = -INFINITY, l0 = 0.f, l1 = 0.f;

    const int rbase = q0 + w * 16 + (lane >> 2);
    const int rmin = q0 + w * 16;
    const int nkv = (q0 >> 6) + 2;

    for (int t = 0; t < nkv; t++) {
        const int cur = t & 1;
        if (t + 1 < nkv) {
            const int k1 = (t + 1) * 64;
            const uint32_t kb = sb + 16384 + (uint32_t)((cur ^ 1) * 8192);
            const uint32_t vb = sb + 32768 + (uint32_t)((cur ^ 1) * 8192);
            #pragma unroll
            for (int it = 0; it < 2; it++) {
                int idx = it * 256 + tid;
                int row = idx >> 3, ch = idx & 7;
                uint32_t soff = sw128((uint32_t)(row * 128 + ch * 16));
                const __half* gk = base + (size_t)(k1 + row) * (3 * EMB) + EMB + h * HD + ch * 8;
                CP16(kb + soff, gk);
                CP16(vb + soff, gk + EMB);
            }
            CP_COMMIT();
        }
        const uint32_t sK = sb + 16384 + (uint32_t)(cur * 8192);
        const uint32_t sV = sb + 32768 + (uint32_t)(cur * 8192);
        const int k0t = t * 64;

        // S = Q K^T
        float s[8][4];
        #pragma unroll
        for (int i = 0; i < 8; i++)
            #pragma unroll
            for (int j = 0; j < 4; j++) s[i][j] = 0.f;
        #pragma unroll
        for (int kk = 0; kk < 4; kk++) {
            #pragma unroll
            for (int g = 0; g < 4; g++) {
                int nrow = g * 16 + ((lane >> 4) << 3) + (lane & 7);
                uint32_t cbhi = (uint32_t)(kk * 2 + ((lane >> 3) & 1));
                uint32_t kf[4];
                LDSM4(kf, sK + (uint32_t)(nrow * 128) + ((cbhi ^ (nrow & 7)) << 4));
                MMAF16(s[2 * g],     qf[kk], kf[0], kf[1]);
                MMAF16(s[2 * g + 1], qf[kk], kf[2], kf[3]);
            }
        }
        // scale 1/sqrt(64)
        #pragma unroll
        for (int i = 0; i < 8; i++)
            #pragma unroll
            for (int j = 0; j < 4; j++) s[i][j] *= 0.125f;

        // causal mask
        if (k0t + 63 > rmin) {
            #pragma unroll
            for (int nf = 0; nf < 8; nf++) {
                int colb = k0t + nf * 8 + ((lane & 3) << 1);
                if (colb > rbase)         s[nf][0] = -INFINITY;
                if (colb + 1 > rbase)     s[nf][1] = -INFINITY;
                if (colb > rbase + 8)     s[nf][2] = -INFINITY;
                if (colb + 1 > rbase + 8) s[nf][3] = -INFINITY;
            }
        }

        // online softmax in registers
        float mx0 = -INFINITY, mx1 = -INFINITY;
        #pragma unroll
        for (int nf = 0; nf < 8; nf++) {
            mx0 = fmaxf(mx0, fmaxf(s[nf][0], s[nf][1]));
            mx1 = fmaxf(mx1, fmaxf(s[nf][2], s[nf][3]));
        }
        mx0 = fmaxf(mx0, __shfl_xor_sync(0xffffffffu, mx0, 1));
        mx0 = fmaxf(mx0, __shfl_xor_sync(0xffffffffu, mx0, 2));
        mx1 = fmaxf(mx1, __shfl_xor_sync(0xffffffffu, mx1, 1));
        mx1 = fmaxf(mx1, __shfl_xor_sync(0xffffffffu, mx1, 2));
        const float mn0 = fmaxf(m0, mx0), mn1 = fmaxf(m1, mx1);
        const float c0 = __expf(m0 - mn0), c1 = __expf(m1 - mn1);
        float sum0 = 0.f, sum1 = 0.f;
        #pragma unroll
        for (int nf = 0; nf < 8; nf++) {
            s[nf][0] = __expf(s[nf][0] - mn0);
            s[nf][1] = __expf(s[nf][1] - mn0);
            s[nf][2] = __expf(s[nf][2] - mn1);
            s[nf][3] = __expf(s[nf][3] - mn1);
            sum0 += s[nf][0] + s[nf][1];
            sum1 += s[nf][2] + s[nf][3];
        }
        sum0 += __shfl_xor_sync(0xffffffffu, sum0, 1);
        sum0 += __shfl_xor_sync(0xffffffffu, sum0, 2);
        sum1 += __shfl_xor_sync(0xffffffffu, sum1, 1);
        sum1 += __shfl_xor_sync(0xffffffffu, sum1, 2);
        l0 = l0 * c0 + sum0;
        l1 = l1 * c1 + sum1;
        m0 = mn0;
        m1 = mn1;
        #pragma unroll
        for (int nf = 0; nf < 8; nf++) {
            o[nf][0] *= c0; o[nf][1] *= c0;
            o[nf][2] *= c1; o[nf][3] *= c1;
        }

        // O += P V
        #pragma unroll
        for (int kk = 0; kk < 4; kk++) {
            uint32_t pf[4];
            pf[0] = pack_f16(s[2 * kk][0],     s[2 * kk][1]);
            pf[1] = pack_f16(s[2 * kk][2],     s[2 * kk][3]);
            pf[2] = pack_f16(s[2 * kk + 1][0], s[2 * kk + 1][1]);
            pf[3] = pack_f16(s[2 * kk + 1][2], s[2 * kk + 1][3]);
            #pragma unroll
            for (int dg = 0; dg < 4; dg++) {
                int row = kk * 16 + (((lane >> 3) & 1) << 3) + (lane & 7);
                int cole = dg * 16 + ((lane >> 4) << 3);
                uint32_t vf[4];
                LDSM4T(vf, sV + sw128((uint32_t)(row * 128 + cole * 2)));
                MMAF16(o[2 * dg],     pf, vf[0], vf[1]);
                MMAF16(o[2 * dg + 1], pf, vf[2], vf[3]);
            }
        }
        if (t + 1 < nkv) {
            CP_WAIT0();
            __syncthreads();
        }
    }

    // epilogue: normalize + fp16 store (head-concat layout)
    const float li0 = 1.f / l0, li1 = 1.f / l1;
    const int row0 = q0 + w * 16 + (lane >> 2);
    #pragma unroll
    for (int nf = 0; nf < 8; nf++) {
        int col = h * HD + nf * 8 + ((lane & 3) << 1);
        *(uint32_t*)(Hout + (size_t)(b * SEQ + row0) * EMB + col) =
            pack_f16(o[nf][0] * li0, o[nf][1] * li0);
        *(uint32_t*)(Hout + (size_t)(b * SEQ + row0 + 8) * EMB + col) =
            pack_f16(o[nf][2] * li1, o[nf][3] * li1);
    }
}

// ================= residual add + layernorm (fp32 out + optional fp16 out) =========
__global__ __launch_bounds__(256) void ln_kernel(
    const float* __restrict__ x, const float* __restrict__ hres,
    const float* __restrict__ g, const float* __restrict__ be,
    float* __restrict__ out, __half* __restrict__ out16)
{
    __shared__ float buf[EMB];
    __shared__ float red[8];
    const int row = blockIdx.x;
    const int tid = threadIdx.x;
    const float* xr = x + (size_t)row * EMB;
    const float* hr = hres + (size_t)row * EMB;

    float s = 0.f;
    for (int e = tid; e < EMB; e += 256) {
        float v = xr[e] + hr[e];
        buf[e] = v;
        s += v;
    }
    #pragma unroll
    for (int o = 16; o; o >>= 1) s += __shfl_down_sync(0xffffffffu, s, o);
    if ((tid & 31) == 0) red[tid >> 5] = s;
    __syncthreads();
    if (tid < 8) {
        s = red[tid];
        #pragma unroll
        for (int o = 4; o; o >>= 1) s += __shfl_down_sync(0xffu, s, o);
        if (tid == 0) red[0] = s;
    }
    __syncthreads();
    const float mu = red[0] * (1.f / EMB);
    __syncthreads();

    float vs = 0.f;
    for (int e = tid; e < EMB; e += 256) {
        float d = buf[e] - mu;
        vs += d * d;
    }
    #pragma unroll
    for (int o = 16; o; o >>= 1) vs += __shfl_down_sync(0xffffffffu, vs, o);
    if ((tid & 31) == 0) red[tid >> 5] = vs;
    __syncthreads();
    if (tid < 8) {
        vs = red[tid];
        #pragma unroll
        for (int o = 4; o; o >>= 1) vs += __shfl_down_sync(0xffu, vs, o);
        if (tid == 0) red[0] = vs;
    }
    __syncthreads();
    const float rstd = rsqrtf(red[0] * (1.f / EMB) + LN_EPS);

    for (int e = tid; e < EMB; e += 256) {
        float v = (buf[e] - mu) * rstd * g[e] + be[e];
        out[(size_t)row * EMB + e] = v;
        if (out16) out16[(size_t)row * EMB + e] = __float2half(v);
    }
}

// ================= launch =================
extern "C" void kernel_launch(void* const* d_in, const int* in_sizes, int n_in,
                              void* d_out, int out_size)
{
    const float* x     = (const float*)d_in[0];
    const float* W_qkv = (const float*)d_in[1];
    const float* b_qkv = (const float*)d_in[2];
    const float* W_out = (const float*)d_in[3];
    const float* b_out = (const float*)d_in[4];
    const float* g1    = (const float*)d_in[5];
    const float* be1   = (const float*)d_in[6];
    const float* W_ff1 = (const float*)d_in[7];
    const float* b_ff1 = (const float*)d_in[8];
    const float* W_ff2 = (const float*)d_in[9];
    const float* b_ff2 = (const float*)d_in[10];
    const float* g2    = (const float*)d_in[11];
    const float* be2   = (const float*)d_in[12];
    float* out = (float*)d_out;

    __half *x16, *qkv16, *attn16, *x116, *ffh16;
    float *tmp, *x1;
    cudaGetSymbolAddress((void**)&x16,    g_x16);
    cudaGetSymbolAddress((void**)&qkv16,  g_qkv16);
    cudaGetSymbolAddress((void**)&attn16, g_attn16);
    cudaGetSymbolAddress((void**)&x116,   g_x116);
    cudaGetSymbolAddress((void**)&ffh16,  g_ffh16);
    cudaGetSymbolAddress((void**)&tmp,    g_tmp);
    cudaGetSymbolAddress((void**)&x1,     g_x1);
    __half *wq, *wo, *w1, *w2;
    cudaGetSymbolAddress((void**)&wq, wt_qkv16);
    cudaGetSymbolAddress((void**)&wo, wt_out16);
    cudaGetSymbolAddress((void**)&w1, wt_ff116);
    cudaGetSymbolAddress((void**)&w2, wt_ff216);

    cudaFuncSetAttribute(gemm_f16, cudaFuncAttributeMaxDynamicSharedMemorySize, GEMM_SMEM);
    cudaFuncSetAttribute(attn_mma, cudaFuncAttributeMaxDynamicSharedMemorySize, 49152);

    // 0) conversions
    xconv_kernel<<<(MROWS * EMB / 4 + 255) / 256, 256>>>(x, x16, MROWS * EMB / 4);
    wconv_kernel<<<dim3(3 * EMB / 32, EMB / 32), dim3(32, 8)>>>(W_qkv, wq, EMB, 3 * EMB);
    wconv_kernel<<<dim3(EMB / 32, EMB / 32),     dim3(32, 8)>>>(W_out, wo, EMB, EMB);
    wconv_kernel<<<dim3(FF_DIM / 32, EMB / 32),  dim3(32, 8)>>>(W_ff1, w1, EMB, FF_DIM);
    wconv_kernel<<<dim3(EMB / 32, FF_DIM / 32),  dim3(32, 8)>>>(W_ff2, w2, FF_DIM, EMB);

    // 1) qkv = x @ W_qkv + b_qkv  (fp16 out only)
    gemm_f16<<<dim3(3 * EMB / 128, MROWS / 128), 256, GEMM_SMEM>>>(
        x16, wq, b_qkv, (float*)0, qkv16, MROWS, 3 * EMB, EMB, 0);

    // 2) causal flash attention (fp16 -> fp16)
    attn_mma<<<dim3(SEQ / 128, NH, BATCH), 256, 49152>>>(qkv16, attn16);

    // 3) proj = attn @ W_out + b_out  (fp32 out)
    gemm_f16<<<dim3(EMB / 128, MROWS / 128), 256, GEMM_SMEM>>>(
        attn16, wo, b_out, tmp, (__half*)0, MROWS, EMB, EMB, 0);

    // 4) x1 = LN(x + proj)  (fp32 + fp16)
    ln_kernel<<<MROWS, 256>>>(x, tmp, g1, be1, x1, x116);

    // 5) ffh = relu(x1 @ W_ff1 + b_ff1)  (fp16 out only)
    gemm_f16<<<dim3(FF_DIM / 128, MROWS / 128), 256, GEMM_SMEM>>>(
        x116, w1, b_ff1, (float*)0, ffh16, MROWS, FF_DIM, EMB, 1);

    // 6) ff = ffh @ W_ff2 + b_ff2  (fp32 out)
    gemm_f16<<<dim3(EMB / 128, MROWS / 128), 256, GEMM_SMEM>>>(
        ffh16, w2, b_ff2, tmp, (__half*)0, MROWS, EMB, FF_DIM, 0);

    // 7) out = LN(x1 + ff)
    ln_kernel<<<MROWS, 256>>>(x1, tmp, g2, be2, out, (__half*)0);
}

// round 7
// speedup vs baseline: 7.7349x; 1.0178x over previous
#include <cuda_runtime.h>
#include <cuda_fp16.h>
#include <math.h>
#include <stdint.h>

#define EMB 1024
#define SEQ 2048
#define BATCH 2
#define NH 16
#define HD 64
#define FF_DIM 2048
#define MROWS (BATCH * SEQ)   // 4096
#define LN_EPS 1e-5f

// ================= helpers (baseline PTX ISA, sm_80-era) =================
__device__ __forceinline__ uint32_t smem_u32(const void* p) {
    uint32_t a;
    asm("{ .reg .u64 t; cvta.to.shared.u64 t, %1; cvt.u32.u64 %0, t; }" : "=r"(a) : "l"(p));
    return a;
}
__device__ __forceinline__ uint32_t sw128(uint32_t off) { return off ^ ((off >> 3) & 0x70); }

#define CP16(dst, src) asm volatile("cp.async.cg.shared.global [%0], [%1], 16;" :: "r"(dst), "l"(src) : "memory")
#define CP_COMMIT()    asm volatile("cp.async.commit_group;" ::: "memory")
#define CP_WAIT0()     asm volatile("cp.async.wait_group 0;" ::: "memory")
#define CP_WAIT1()     asm volatile("cp.async.wait_group 1;" ::: "memory")

#define LDSM4(r, addr) \
    asm volatile("ldmatrix.sync.aligned.m8n8.x4.shared.b16 {%0,%1,%2,%3}, [%4];" \
        : "=r"((r)[0]), "=r"((r)[1]), "=r"((r)[2]), "=r"((r)[3]) : "r"(addr))
#define LDSM4T(r, addr) \
    asm volatile("ldmatrix.sync.aligned.m8n8.x4.trans.shared.b16 {%0,%1,%2,%3}, [%4];" \
        : "=r"((r)[0]), "=r"((r)[1]), "=r"((r)[2]), "=r"((r)[3]) : "r"(addr))

#define MMAF16(d, a, b0, b1) \
    asm volatile("mma.sync.aligned.m16n8k16.row.col.f32.f16.f16.f32 " \
        "{%0,%1,%2,%3},{%4,%5,%6,%7},{%8,%9},{%0,%1,%2,%3};" \
        : "+f"((d)[0]), "+f"((d)[1]), "+f"((d)[2]), "+f"((d)[3]) \
        : "r"((a)[0]), "r"((a)[1]), "r"((a)[2]), "r"((a)[3]), "r"(b0), "r"(b1))

__device__ __forceinline__ uint32_t pack_f16(float a, float b) {
    __half2 t = __floats2half2_rn(a, b);
    return *(uint32_t*)&t;
}

// ================= scratch =================
__device__ __half g_x16[(size_t)MROWS * EMB];
__device__ __half g_qkv16[(size_t)MROWS * 3 * EMB];
__device__ __half g_attn16[(size_t)MROWS * EMB];
__device__ __half g_x116[(size_t)MROWS * EMB];
__device__ __half g_ffh16[(size_t)MROWS * FF_DIM];
__device__ float  g_tmp[(size_t)MROWS * EMB];
__device__ float  g_x1[(size_t)MROWS * EMB];
__device__ __half wt_qkv16[(size_t)3 * EMB * EMB];
__device__ __half wt_out16[(size_t)EMB * EMB];
__device__ __half wt_ff116[(size_t)FF_DIM * EMB];
__device__ __half wt_ff216[(size_t)EMB * FF_DIM];

// ============ weight transpose fp32[K,N] -> fp16[N,K] ============
__global__ __launch_bounds__(256) void wconv_kernel(
    const float* __restrict__ W, __half* __restrict__ T, int K, int N)
{
    __shared__ float sm[32][33];
    const int tx = threadIdx.x, ty = threadIdx.y;
    const int n0 = blockIdx.x * 32, k0 = blockIdx.y * 32;
    #pragma unroll
    for (int i = 0; i < 4; i++)
        sm[ty + i * 8][tx] = W[(size_t)(k0 + ty + i * 8) * N + n0 + tx];
    __syncthreads();
    #pragma unroll
    for (int i = 0; i < 4; i++) {
        int nl = ty + i * 8;
        T[(size_t)(n0 + nl) * K + k0 + tx] = __float2half(sm[tx][nl]);
    }
}

// ============ x fp32 -> fp16 ============
__global__ __launch_bounds__(256) void xconv_kernel(
    const float* __restrict__ x, __half* __restrict__ x16, int n4)
{
    int i = blockIdx.x * 256 + threadIdx.x;
    if (i < n4) {
        float4 v = *(const float4*)(x + (size_t)i * 4);
        uint2 p = make_uint2(pack_f16(v.x, v.y), pack_f16(v.z, v.w));
        *(uint2*)(x16 + (size_t)i * 4) = p;
    }
}

// ============ fp16 HMMA GEMM: C = A[M,K] @ B[N,K]^T + bias ============
// CTA tile 128x256, BK=64, 3-stage cp.async pipeline. 512 threads (16 warps, 4Mx4N),
// warp tile 32x64.
#define GT_STAGE 49152        // A 16K @0 | B 32K @16K
#define GOFF_B 16384
#define GEMM_SMEM (3 * GT_STAGE)

__device__ __forceinline__ void g_cpA(
    const __half* __restrict__ A, uint32_t st, int K, int m0, int kc, int tid)
{
    #pragma unroll
    for (int it = 0; it < 2; it++) {
        int idx = it * 512 + tid;
        int row = idx >> 3, ch = idx & 7;
        CP16(st + sw128((uint32_t)(row * 128 + ch * 16)),
             A + (size_t)(m0 + row) * K + kc + ch * 8);
    }
}
__device__ __forceinline__ void g_cpB(
    const __half* __restrict__ B, uint32_t st, int K, int n0, int kc, int tid)
{
    #pragma unroll
    for (int it = 0; it < 4; it++) {
        int idx = it * 512 + tid;
        int row = idx >> 3, ch = idx & 7;
        CP16(st + GOFF_B + sw128((uint32_t)(row * 128 + ch * 16)),
             B + (size_t)(n0 + row) * K + kc + ch * 8);
    }
}

__global__ __launch_bounds__(512, 1) void gemm_f16(
    const __half* __restrict__ A, const __half* __restrict__ B,
    const float* __restrict__ bias, float* __restrict__ C32,
    __half* __restrict__ C16, int M, int N, int K, int relu)
{
    extern __shared__ char sm[];
    const uint32_t smb = smem_u32(sm);
    const int tid = threadIdx.x, wid = tid >> 5, lane = tid & 31;
    const int m0 = blockIdx.y * 128, n0 = blockIdx.x * 256;
    const int wm = (wid & 3) * 32, wn = (wid >> 2) * 64;
    const int NC = K >> 6;

    float acc[2][8][4];
    #pragma unroll
    for (int i = 0; i < 2; i++)
        #pragma unroll
        for (int j = 0; j < 8; j++)
            #pragma unroll
            for (int q = 0; q < 4; q++) acc[i][j][q] = 0.f;

    // prologue: stages 0 and 1 in flight
    g_cpA(A, smb, K, m0, 0, tid);
    g_cpB(B, smb, K, n0, 0, tid);
    CP_COMMIT();
    g_cpA(A, smb + GT_STAGE, K, m0, 64, tid);
    g_cpB(B, smb + GT_STAGE, K, n0, 64, tid);
    CP_COMMIT();

    int sidx = 0;
    for (int c = 0; c < NC; c++) {
        if (c + 2 < NC) CP_WAIT1(); else CP_WAIT0();
        __syncthreads();
        if (c + 2 < NC) {
            int ns = sidx + 2; if (ns >= 3) ns -= 3;
            const uint32_t st = smb + (uint32_t)ns * GT_STAGE;
            g_cpA(A, st, K, m0, (c + 2) << 6, tid);
            g_cpB(B, st, K, n0, (c + 2) << 6, tid);
            CP_COMMIT();
        }
        const uint32_t s0 = smb + (uint32_t)sidx * GT_STAGE;
        #pragma unroll
        for (int kk = 0; kk < 4; kk++) {
            uint32_t af[2][4];
            #pragma unroll
            for (int mt = 0; mt < 2; mt++) {
                int row = wm + mt * 16 + (lane & 15);
                uint32_t cbhi = (uint32_t)(kk * 2 + (lane >> 4));
                LDSM4(af[mt], s0 + (uint32_t)(row * 128) + ((cbhi ^ (row & 7)) << 4));
            }
            #pragma unroll
            for (int g = 0; g < 4; g++) {
                int nrow = wn + g * 16 + ((lane >> 4) << 3) + (lane & 7);
                uint32_t cbhi = (uint32_t)(kk * 2 + ((lane >> 3) & 1));
                uint32_t bf[4];
                LDSM4(bf, s0 + GOFF_B + (uint32_t)(nrow * 128) + ((cbhi ^ (nrow & 7)) << 4));
                #pragma unroll
                for (int mt = 0; mt < 2; mt++) {
                    MMAF16(acc[mt][2 * g],     af[mt], bf[0], bf[1]);
                    MMAF16(acc[mt][2 * g + 1], af[mt], bf[2], bf[3]);
                }
            }
        }
        if (++sidx >= 3) sidx -= 3;
    }

    // epilogue: bias + optional relu; fp32 and/or fp16 outputs
    #pragma unroll
    for (int mt = 0; mt < 2; mt++) {
        #pragma unroll
        for (int nt = 0; nt < 8; nt++) {
            int r0 = m0 + wm + mt * 16 + (lane >> 2);
            int col = n0 + wn + nt * 8 + (lane & 3) * 2;
            float2 bb = *(const float2*)(bias + col);
            float v0 = acc[mt][nt][0] + bb.x;
            float v1 = acc[mt][nt][1] + bb.y;
            float v2 = acc[mt][nt][2] + bb.x;
            float v3 = acc[mt][nt][3] + bb.y;
            if (relu) {
                v0 = fmaxf(v0, 0.f); v1 = fmaxf(v1, 0.f);
                v2 = fmaxf(v2, 0.f); v3 = fmaxf(v3, 0.f);
            }
            if (C32) {
                *(float2*)(C32 + (size_t)r0 * N + col) = make_float2(v0, v1);
                *(float2*)(C32 + (size_t)(r0 + 8) * N + col) = make_float2(v2, v3);
            }
            if (C16) {
                *(uint32_t*)(C16 + (size_t)r0 * N + col) = pack_f16(v0, v1);
                *(uint32_t*)(C16 + (size_t)(r0 + 8) * N + col) = pack_f16(v2, v3);
            }
        }
    }
}

// ================= flash attention: fp16 in/out, double-buffered KV =================
__global__ __launch_bounds__(256, 2) void attn_mma(
    const __half* __restrict__ qkv, __half* __restrict__ Hout)
{
    extern __shared__ char sma[];
    const uint32_t sb = smem_u32(sma);

    const int tid = threadIdx.x, lane = tid & 31, w = tid >> 5;
    const int qb = blockIdx.x, h = blockIdx.y, b = blockIdx.z;
    const int q0 = qb * 128;
    const __half* base = qkv + (size_t)b * SEQ * 3 * EMB;

    #pragma unroll
    for (int it = 0; it < 4; it++) {
        int idx = it * 256 + tid;
        int row = idx >> 3, ch = idx & 7;
        CP16(sb + sw128((uint32_t)(row * 128 + ch * 16)),
             base + (size_t)(q0 + row) * (3 * EMB) + h * HD + ch * 8);
    }
    #pragma unroll
    for (int it = 0; it < 2; it++) {
        int idx = it * 256 + tid;
        int row = idx >> 3, ch = idx & 7;
        uint32_t soff = sw128((uint32_t)(row * 128 + ch * 16));
        const __half* gk = base + (size_t)row * (3 * EMB) + EMB + h * HD + ch * 8;
        CP16(sb + 16384 + soff, gk);
        CP16(sb + 32768 + soff, gk + EMB);
    }
    CP_COMMIT();
    CP_WAIT0();
    __syncthreads();

    uint32_t qf[4][4];
    #pragma unroll
    for (int kk = 0; kk < 4; kk++) {
        int row = w * 16 + (lane & 15);
        uint32_t cbhi = (uint32_t)(kk * 2 + (lane >> 4));
        LDSM4(qf[kk], sb + (uint32_t)(row * 128) + ((cbhi ^ (row & 7)) << 4));
    }

    float o[8][4];
    #pragma unroll
    for (int i = 0; i < 8; i++)
        #pragma unroll
        for (int j = 0; j < 4; j++) o[i][j] = 0.f;
    float m0 = -INFINITY, m1 = -INFINITY, l0 = 0.f, l1 = 0.f;

    const int rbase = q0 + w * 16 + (lane >> 2);
    const int rmin = q0 + w * 16;
    const int nkv = (q0 >> 6) + 2;

    for (int t = 0; t < nkv; t++) {
        const int cur = t & 1;
        if (t + 1 < nkv) {
            const int k1 = (t + 1) * 64;
            const uint32_t kb = sb + 16384 + (uint32_t)((cur ^ 1) * 8192);
            const uint32_t vb = sb + 32768 + (uint32_t)((cur ^ 1) * 8192);
            #pragma unroll
            for (int it = 0; it < 2; it++) {
                int idx = it * 256 + tid;
                int row = idx >> 3, ch = idx & 7;
                uint32_t soff = sw128((uint32_t)(row * 128 + ch * 16));
                const __half* gk = base + (size_t)(k1 + row) * (3 * EMB) + EMB + h * HD + ch * 8;
                CP16(kb + soff, gk);
                CP16(vb + soff, gk + EMB);
            }
            CP_COMMIT();
        }
        const uint32_t sK = sb + 16384 + (uint32_t)(cur * 8192);
        const uint32_t sV = sb + 32768 + (uint32_t)(cur * 8192);
        const int k0t = t * 64;

        float s[8][4];
        #pragma unroll
        for (int i = 0; i < 8; i++)
            #pragma unroll
            for (int j = 0; j < 4; j++) s[i][j] = 0.f;
        #pragma unroll
        for (int kk = 0; kk < 4; kk++) {
            #pragma unroll
            for (int g = 0; g < 4; g++) {
                int nrow = g * 16 + ((lane >> 4) << 3) + (lane & 7);
                uint32_t cbhi = (uint32_t)(kk * 2 + ((lane >> 3) & 1));
                uint32_t kf[4];
                LDSM4(kf, sK + (uint32_t)(nrow * 128) + ((cbhi ^ (nrow & 7)) << 4));
                MMAF16(s[2 * g],     qf[kk], kf[0], kf[1]);
                MMAF16(s[2 * g + 1], qf[kk], kf[2], kf[3]);
            }
        }
        #pragma unroll
        for (int i = 0; i < 8; i++)
            #pragma unroll
            for (int j = 0; j < 4; j++) s[i][j] *= 0.125f;

        if (k0t + 63 > rmin) {
            #pragma unroll
            for (int nf = 0; nf < 8; nf++) {
                int colb = k0t + nf * 8 + ((lane & 3) << 1);
                if (colb > rbase)         s[nf][0] = -INFINITY;
                if (colb + 1 > rbase)     s[nf][1] = -INFINITY;
                if (colb > rbase + 8)     s[nf][2] = -INFINITY;
                if (colb + 1 > rbase + 8) s[nf][3] = -INFINITY;
            }
        }

        float mx0 = -INFINITY, mx1 = -INFINITY;
        #pragma unroll
        for (int nf = 0; nf < 8; nf++) {
            mx0 = fmaxf(mx0, fmaxf(s[nf][0], s[nf][1]));
            mx1 = fmaxf(mx1, fmaxf(s[nf][2], s[nf][3]));
        }
        mx0 = fmaxf(mx0, __shfl_xor_sync(0xffffffffu, mx0, 1));
        mx0 = fmaxf(mx0, __shfl_xor_sync(0xffffffffu, mx0, 2));
        mx1 = fmaxf(mx1, __shfl_xor_sync(0xffffffffu, mx1, 1));
        mx1 = fmaxf(mx1, __shfl_xor_sync(0xffffffffu, mx1, 2));
        const float mn0 = fmaxf(m0, mx0), mn1 = fmaxf(m1, mx1);
        const float c0 = __expf(m0 - mn0), c1 = __expf(m1 - mn1);
        float sum0 = 0.f, sum1 = 0.f;
        #pragma unroll
        for (int nf = 0; nf < 8; nf++) {
            s[nf][0] = __expf(s[nf][0] - mn0);
            s[nf][1] = __expf(s[nf][1] - mn0);
            s[nf][2] = __expf(s[nf][2] - mn1);
            s[nf][3] = __expf(s[nf][3] - mn1);
            sum0 += s[nf][0] + s[nf][1];
            sum1 += s[nf][2] + s[nf][3];
        }
        sum0 += __shfl_xor_sync(0xffffffffu, sum0, 1);
        sum0 += __shfl_xor_sync(0xffffffffu, sum0, 2);
        sum1 += __shfl_xor_sync(0xffffffffu, sum1, 1);
        sum1 += __shfl_xor_sync(0xffffffffu, sum1, 2);
        l0 = l0 * c0 + sum0;
        l1 = l1 * c1 + sum1;
        m0 = mn0;
        m1 = mn1;
        #pragma unroll
        for (int nf = 0; nf < 8; nf++) {
            o[nf][0] *= c0; o[nf][1] *= c0;
            o[nf][2] *= c1; o[nf][3] *= c1;
        }

        #pragma unroll
        for (int kk = 0; kk < 4; kk++) {
            uint32_t pf[4];
            pf[0] = pack_f16(s[2 * kk][0],     s[2 * kk][1]);
            pf[1] = pack_f16(s[2 * kk][2],     s[2 * kk][3]);
            pf[2] = pack_f16(s[2 * kk + 1][0], s[2 * kk + 1][1]);
            pf[3] = pack_f16(s[2 * kk + 1][2], s[2 * kk + 1][3]);
            #pragma unroll
            for (int dg = 0; dg < 4; dg++) {
                int row = kk * 16 + (((lane >> 3) & 1) << 3) + (lane & 7);
                int cole = dg * 16 + ((lane >> 4) << 3);
                uint32_t vf[4];
                LDSM4T(vf, sV + sw128((uint32_t)(row * 128 + cole * 2)));
                MMAF16(o[2 * dg],     pf, vf[0], vf[1]);
                MMAF16(o[2 * dg + 1], pf, vf[2], vf[3]);
            }
        }
        if (t + 1 < nkv) {
            CP_WAIT0();
            __syncthreads();
        }
    }

    const float li0 = 1.f / l0, li1 = 1.f / l1;
    const int row0 = q0 + w * 16 + (lane >> 2);
    #pragma unroll
    for (int nf = 0; nf < 8; nf++) {
        int col = h * HD + nf * 8 + ((lane & 3) << 1);
        *(uint32_t*)(Hout + (size_t)(b * SEQ + row0) * EMB + col) =
            pack_f16(o[nf][0] * li0, o[nf][1] * li0);
        *(uint32_t*)(Hout + (size_t)(b * SEQ + row0 + 8) * EMB + col) =
            pack_f16(o[nf][2] * li1, o[nf][3] * li1);
    }
}

// ============ residual add + layernorm, one pass (sum + sumsq), regs-resident ======
__global__ __launch_bounds__(256) void ln_kernel(
    const float* __restrict__ x, const float* __restrict__ hres,
    const float* __restrict__ g, const float* __restrict__ be,
    float* __restrict__ out, __half* __restrict__ out16)
{
    __shared__ float red[16];
    const int row = blockIdx.x;
    const int tid = threadIdx.x;
    const float* xr = x + (size_t)row * EMB;
    const float* hr = hres + (size_t)row * EMB;

    // each thread owns 4 consecutive floats
    float4 xv = *(const float4*)(xr + tid * 4);
    float4 hv = *(const float4*)(hr + tid * 4);
    float v0 = xv.x + hv.x, v1 = xv.y + hv.y, v2 = xv.z + hv.z, v3 = xv.w + hv.w;

    float s = v0 + v1 + v2 + v3;
    float q = v0 * v0 + v1 * v1 + v2 * v2 + v3 * v3;
    #pragma unroll
    for (int o = 16; o; o >>= 1) {
        s += __shfl_down_sync(0xffffffffu, s, o);
        q += __shfl_down_sync(0xffffffffu, q, o);
    }
    if ((tid & 31) == 0) { red[tid >> 5] = s; red[8 + (tid >> 5)] = q; }
    __syncthreads();
    if (tid < 8) {
        s = red[tid];
        q = red[8 + tid];
        #pragma unroll
        for (int o = 4; o; o >>= 1) {
            s += __shfl_down_sync(0xffu, s, o);
            q += __shfl_down_sync(0xffu, q, o);
        }
        if (tid == 0) { red[0] = s; red[8] = q; }
    }
    __syncthreads();
    const float mu = red[0] * (1.f / EMB);
    const float var = red[8] * (1.f / EMB) - mu * mu;
    const float rstd = rsqrtf(var + LN_EPS);

    float4 gv = *(const float4*)(g + tid * 4);
    float4 bv = *(const float4*)(be + tid * 4);
    float o0 = (v0 - mu) * rstd * gv.x + bv.x;
    float o1 = (v1 - mu) * rstd * gv.y + bv.y;
    float o2 = (v2 - mu) * rstd * gv.z + bv.z;
    float o3 = (v3 - mu) * rstd * gv.w + bv.w;
    *(float4*)(out + (size_t)row * EMB + tid * 4) = make_float4(o0, o1, o2, o3);
    if (out16) {
        *(uint2*)(out16 + (size_t)row * EMB + tid * 4) =
            make_uint2(pack_f16(o0, o1), pack_f16(o2, o3));
    }
}

// ================= launch =================
extern "C" void kernel_launch(void* const* d_in, const int* in_sizes, int n_in,
                              void* d_out, int out_size)
{
    const float* x     = (const float*)d_in[0];
    const float* W_qkv = (const float*)d_in[1];
    const float* b_qkv = (const float*)d_in[2];
    const float* W_out = (const float*)d_in[3];
    const float* b_out = (const float*)d_in[4];
    const float* g1    = (const float*)d_in[5];
    const float* be1   = (const float*)d_in[6];
    const float* W_ff1 = (const float*)d_in[7];
    const float* b_ff1 = (const float*)d_in[8];
    const float* W_ff2 = (const float*)d_in[9];
    const float* b_ff2 = (const float*)d_in[10];
    const float* g2    = (const float*)d_in[11];
    const float* be2   = (const float*)d_in[12];
    float* out = (float*)d_out;

    __half *x16, *qkv16, *attn16, *x116, *ffh16;
    float *tmp, *x1;
    cudaGetSymbolAddress((void**)&x16,    g_x16);
    cudaGetSymbolAddress((void**)&qkv16,  g_qkv16);
    cudaGetSymbolAddress((void**)&attn16, g_attn16);
    cudaGetSymbolAddress((void**)&x116,   g_x116);
    cudaGetSymbolAddress((void**)&ffh16,  g_ffh16);
    cudaGetSymbolAddress((void**)&tmp,    g_tmp);
    cudaGetSymbolAddress((void**)&x1,     g_x1);
    __half *wq, *wo, *w1, *w2;
    cudaGetSymbolAddress((void**)&wq, wt_qkv16);
    cudaGetSymbolAddress((void**)&wo, wt_out16);
    cudaGetSymbolAddress((void**)&w1, wt_ff116);
    cudaGetSymbolAddress((void**)&w2, wt_ff216);

    cudaFuncSetAttribute(gemm_f16, cudaFuncAttributeMaxDynamicSharedMemorySize, GEMM_SMEM);
    cudaFuncSetAttribute(attn_mma, cudaFuncAttributeMaxDynamicSharedMemorySize, 49152);

    // 0) conversions
    xconv_kernel<<<(MROWS * EMB / 4 + 255) / 256, 256>>>(x, x16, MROWS * EMB / 4);
    wconv_kernel<<<dim3(3 * EMB / 32, EMB / 32), dim3(32, 8)>>>(W_qkv, wq, EMB, 3 * EMB);
    wconv_kernel<<<dim3(EMB / 32, EMB / 32),     dim3(32, 8)>>>(W_out, wo, EMB, EMB);
    wconv_kernel<<<dim3(FF_DIM / 32, EMB / 32),  dim3(32, 8)>>>(W_ff1, w1, EMB, FF_DIM);
    wconv_kernel<<<dim3(EMB / 32, FF_DIM / 32),  dim3(32, 8)>>>(W_ff2, w2, FF_DIM, EMB);

    // 1) qkv = x @ W_qkv + b_qkv  (fp16 out only)
    gemm_f16<<<dim3(3 * EMB / 256, MROWS / 128), 512, GEMM_SMEM>>>(
        x16, wq, b_qkv, (float*)0, qkv16, MROWS, 3 * EMB, EMB, 0);

    // 2) causal flash attention (fp16 -> fp16)
    attn_mma<<<dim3(SEQ / 128, NH, BATCH), 256, 49152>>>(qkv16, attn16);

    // 3) proj = attn @ W_out + b_out  (fp32 out)
    gemm_f16<<<dim3(EMB / 256, MROWS / 128), 512, GEMM_SMEM>>>(
        attn16, wo, b_out, tmp, (__half*)0, MROWS, EMB, EMB, 0);

    // 4) x1 = LN(x + proj)  (fp32 + fp16)
    ln_kernel<<<MROWS, 256>>>(x, tmp, g1, be1, x1, x116);

    // 5) ffh = relu(x1 @ W_ff1 + b_ff1)  (fp16 out only)
    gemm_f16<<<dim3(FF_DIM / 256, MROWS / 128), 512, GEMM_SMEM>>>(
        x116, w1, b_ff1, (float*)0, ffh16, MROWS, FF_DIM, EMB, 1);

    // 6) ff = ffh @ W_ff2 + b_ff2  (fp32 out)
    gemm_f16<<<dim3(EMB / 256, MROWS / 128), 512, GEMM_SMEM>>>(
        ffh16, w2, b_ff2, tmp, (__half*)0, MROWS, EMB, FF_DIM, 0);

    // 7) out = LN(x1 + ff)
    ln_kernel<<<MROWS, 256>>>(x1, tmp, g2, be2, out, (__half*)0);
}

// round 9
// speedup vs baseline: 7.8433x; 1.0140x over previous
#include <cuda_runtime.h>
#include <cuda_fp16.h>
#include <math.h>
#include <stdint.h>

#define EMB 1024
#define SEQ 2048
#define BATCH 2
#define NH 16
#define HD 64
#define FF_DIM 2048
#define MROWS (BATCH * SEQ)   // 4096
#define LN_EPS 1e-5f

// ================= helpers (baseline PTX ISA, sm_80-era) =================
__device__ __forceinline__ uint32_t smem_u32(const void* p) {
    uint32_t a;
    asm("{ .reg .u64 t; cvta.to.shared.u64 t, %1; cvt.u32.u64 %0, t; }" : "=r"(a) : "l"(p));
    return a;
}
__device__ __forceinline__ uint32_t sw128(uint32_t off) { return off ^ ((off >> 3) & 0x70); }

#define CP16(dst, src) asm volatile("cp.async.cg.shared.global [%0], [%1], 16;" :: "r"(dst), "l"(src) : "memory")
#define CP_COMMIT()    asm volatile("cp.async.commit_group;" ::: "memory")
#define CP_WAIT0()     asm volatile("cp.async.wait_group 0;" ::: "memory")
#define CP_WAIT1()     asm volatile("cp.async.wait_group 1;" ::: "memory")

#define LDSM4(r, addr) \
    asm volatile("ldmatrix.sync.aligned.m8n8.x4.shared.b16 {%0,%1,%2,%3}, [%4];" \
        : "=r"((r)[0]), "=r"((r)[1]), "=r"((r)[2]), "=r"((r)[3]) : "r"(addr))
#define LDSM4T(r, addr) \
    asm volatile("ldmatrix.sync.aligned.m8n8.x4.trans.shared.b16 {%0,%1,%2,%3}, [%4];" \
        : "=r"((r)[0]), "=r"((r)[1]), "=r"((r)[2]), "=r"((r)[3]) : "r"(addr))

#define MMAF16(d, a, b0, b1) \
    asm volatile("mma.sync.aligned.m16n8k16.row.col.f32.f16.f16.f32 " \
        "{%0,%1,%2,%3},{%4,%5,%6,%7},{%8,%9},{%0,%1,%2,%3};" \
        : "+f"((d)[0]), "+f"((d)[1]), "+f"((d)[2]), "+f"((d)[3]) \
        : "r"((a)[0]), "r"((a)[1]), "r"((a)[2]), "r"((a)[3]), "r"(b0), "r"(b1))

__device__ __forceinline__ uint32_t pack_f16(float a, float b) {
    __half2 t = __floats2half2_rn(a, b);
    return *(uint32_t*)&t;
}

// ================= scratch =================
__device__ __half g_x16[(size_t)MROWS * EMB];
__device__ __half g_qkv16[(size_t)MROWS * 3 * EMB];
__device__ __half g_attn16[(size_t)MROWS * EMB];
__device__ __half g_x116[(size_t)MROWS * EMB];
__device__ __half g_ffh16[(size_t)MROWS * FF_DIM];
__device__ float  g_tmp[(size_t)MROWS * EMB];
__device__ float  g_x1[(size_t)MROWS * EMB];
__device__ __half wt_qkv16[(size_t)3 * EMB * EMB];
__device__ __half wt_out16[(size_t)EMB * EMB];
__device__ __half wt_ff116[(size_t)FF_DIM * EMB];
__device__ __half wt_ff216[(size_t)EMB * FF_DIM];

// ============ merged conversions: 4 weight transposes + x fp32->fp16 ============
// blocks [0,3072)   : W_qkv  K=1024 N=3072  (96 x 32)
// blocks [3072,4096): W_out  K=1024 N=1024  (32 x 32)
// blocks [4096,6144): W_ff1  K=1024 N=2048  (64 x 32)
// blocks [6144,8192): W_ff2  K=2048 N=1024  (32 x 64)
// blocks [8192,12288): xconv (1 block = 1024 elements)
__global__ __launch_bounds__(256) void conv_all(
    const float* __restrict__ Wq, __half* __restrict__ Tq,
    const float* __restrict__ Wo, __half* __restrict__ To,
    const float* __restrict__ W1, __half* __restrict__ T1,
    const float* __restrict__ W2, __half* __restrict__ T2,
    const float* __restrict__ x, __half* __restrict__ x16)
{
    const int bid = blockIdx.x;
    const int tx = threadIdx.x & 31, ty = threadIdx.x >> 5;

    if (bid >= 8192) {
        int i = (bid - 8192) * 256 + threadIdx.x;
        float4 v = *(const float4*)(x + (size_t)i * 4);
        *(uint2*)(x16 + (size_t)i * 4) = make_uint2(pack_f16(v.x, v.y), pack_f16(v.z, v.w));
        return;
    }

    const float* W; __half* T;
    int K, N, bx, by;
    if (bid < 3072)      { W = Wq; T = Tq; K = 1024; N = 3072; bx = bid % 96;          by = bid / 96; }
    else if (bid < 4096) { W = Wo; T = To; K = 1024; N = 1024; bx = (bid - 3072) % 32; by = (bid - 3072) / 32; }
    else if (bid < 6144) { W = W1; T = T1; K = 1024; N = 2048; bx = (bid - 4096) % 64; by = (bid - 4096) / 64; }
    else                 { W = W2; T = T2; K = 2048; N = 1024; bx = (bid - 6144) % 32; by = (bid - 6144) / 32; }

    __shared__ float sm[32][33];
    const int n0 = bx * 32, k0 = by * 32;
    #pragma unroll
    for (int i = 0; i < 4; i++)
        sm[ty + i * 8][tx] = W[(size_t)(k0 + ty + i * 8) * N + n0 + tx];
    __syncthreads();
    #pragma unroll
    for (int i = 0; i < 4; i++) {
        int nl = ty + i * 8;
        T[(size_t)(n0 + nl) * K + k0 + tx] = __float2half(sm[tx][nl]);
    }
}

// ============ fp16 HMMA GEMM: C = A[M,K] @ B[N,K]^T + bias ============
// CTA tile 128x256, BK=64, 3-stage cp.async pipeline. 512 threads (16 warps, 4Mx4N).
#define GT_STAGE 49152        // A 16K @0 | B 32K @16K
#define GOFF_B 16384
#define GEMM_SMEM (3 * GT_STAGE)

__device__ __forceinline__ void g_cpA(
    const __half* __restrict__ A, uint32_t st, int K, int m0, int kc, int tid)
{
    #pragma unroll
    for (int it = 0; it < 2; it++) {
        int idx = it * 512 + tid;
        int row = idx >> 3, ch = idx & 7;
        CP16(st + sw128((uint32_t)(row * 128 + ch * 16)),
             A + (size_t)(m0 + row) * K + kc + ch * 8);
    }
}
__device__ __forceinline__ void g_cpB(
    const __half* __restrict__ B, uint32_t st, int K, int n0, int kc, int tid)
{
    #pragma unroll
    for (int it = 0; it < 4; it++) {
        int idx = it * 512 + tid;
        int row = idx >> 3, ch = idx & 7;
        CP16(st + GOFF_B + sw128((uint32_t)(row * 128 + ch * 16)),
             B + (size_t)(n0 + row) * K + kc + ch * 8);
    }
}

__global__ __launch_bounds__(512, 1) void gemm_f16(
    const __half* __restrict__ A, const __half* __restrict__ B,
    const float* __restrict__ bias, float* __restrict__ C32,
    __half* __restrict__ C16, int M, int N, int K, int relu)
{
    extern __shared__ char sm[];
    const uint32_t smb = smem_u32(sm);
    const int tid = threadIdx.x, wid = tid >> 5, lane = tid & 31;
    const int m0 = blockIdx.y * 128, n0 = blockIdx.x * 256;
    const int wm = (wid & 3) * 32, wn = (wid >> 2) * 64;
    const int NC = K >> 6;

    float acc[2][8][4];
    #pragma unroll
    for (int i = 0; i < 2; i++)
        #pragma unroll
        for (int j = 0; j < 8; j++)
            #pragma unroll
            for (int q = 0; q < 4; q++) acc[i][j][q] = 0.f;

    g_cpA(A, smb, K, m0, 0, tid);
    g_cpB(B, smb, K, n0, 0, tid);
    CP_COMMIT();
    g_cpA(A, smb + GT_STAGE, K, m0, 64, tid);
    g_cpB(B, smb + GT_STAGE, K, n0, 64, tid);
    CP_COMMIT();

    int sidx = 0;
    for (int c = 0; c < NC; c++) {
        if (c + 2 < NC) CP_WAIT1(); else CP_WAIT0();
        __syncthreads();
        if (c + 2 < NC) {
            int ns = sidx + 2; if (ns >= 3) ns -= 3;
            const uint32_t st = smb + (uint32_t)ns * GT_STAGE;
            g_cpA(A, st, K, m0, (c + 2) << 6, tid);
            g_cpB(B, st, K, n0, (c + 2) << 6, tid);
            CP_COMMIT();
        }
        const uint32_t s0 = smb + (uint32_t)sidx * GT_STAGE;
        #pragma unroll
        for (int kk = 0; kk < 4; kk++) {
            uint32_t af[2][4];
            #pragma unroll
            for (int mt = 0; mt < 2; mt++) {
                int row = wm + mt * 16 + (lane & 15);
                uint32_t cbhi = (uint32_t)(kk * 2 + (lane >> 4));
                LDSM4(af[mt], s0 + (uint32_t)(row * 128) + ((cbhi ^ (row & 7)) << 4));
            }
            #pragma unroll
            for (int g = 0; g < 4; g++) {
                int nrow = wn + g * 16 + ((lane >> 4) << 3) + (lane & 7);
                uint32_t cbhi = (uint32_t)(kk * 2 + ((lane >> 3) & 1));
                uint32_t bf[4];
                LDSM4(bf, s0 + GOFF_B + (uint32_t)(nrow * 128) + ((cbhi ^ (nrow & 7)) << 4));
                #pragma unroll
                for (int mt = 0; mt < 2; mt++) {
                    MMAF16(acc[mt][2 * g],     af[mt], bf[0], bf[1]);
                    MMAF16(acc[mt][2 * g + 1], af[mt], bf[2], bf[3]);
                }
            }
        }
        if (++sidx >= 3) sidx -= 3;
    }

    #pragma unroll
    for (int mt = 0; mt < 2; mt++) {
        #pragma unroll
        for (int nt = 0; nt < 8; nt++) {
            int r0 = m0 + wm + mt * 16 + (lane >> 2);
            int col = n0 + wn + nt * 8 + (lane & 3) * 2;
            float2 bb = *(const float2*)(bias + col);
            float v0 = acc[mt][nt][0] + bb.x;
            float v1 = acc[mt][nt][1] + bb.y;
            float v2 = acc[mt][nt][2] + bb.x;
            float v3 = acc[mt][nt][3] + bb.y;
            if (relu) {
                v0 = fmaxf(v0, 0.f); v1 = fmaxf(v1, 0.f);
                v2 = fmaxf(v2, 0.f); v3 = fmaxf(v3, 0.f);
            }
            if (C32) {
                *(float2*)(C32 + (size_t)r0 * N + col) = make_float2(v0, v1);
                *(float2*)(C32 + (size_t)(r0 + 8) * N + col) = make_float2(v2, v3);
            }
            if (C16) {
                *(uint32_t*)(C16 + (size_t)r0 * N + col) = pack_f16(v0, v1);
                *(uint32_t*)(C16 + (size_t)(r0 + 8) * N + col) = pack_f16(v2, v3);
            }
        }
    }
}

// ================= flash attention: fp16 in/out, LPT order, masked-warp skip ========
__global__ __launch_bounds__(256, 2) void attn_mma(
    const __half* __restrict__ qkv, __half* __restrict__ Hout)
{
    extern __shared__ char sma[];
    const uint32_t sb = smem_u32(sma);

    const int tid = threadIdx.x, lane = tid & 31, w = tid >> 5;
    const int qb = gridDim.x - 1 - blockIdx.x;   // LPT: longest CTAs first
    const int h = blockIdx.y, b = blockIdx.z;
    const int q0 = qb * 128;
    const __half* base = qkv + (size_t)b * SEQ * 3 * EMB;

    #pragma unroll
    for (int it = 0; it < 4; it++) {
        int idx = it * 256 + tid;
        int row = idx >> 3, ch = idx & 7;
        CP16(sb + sw128((uint32_t)(row * 128 + ch * 16)),
             base + (size_t)(q0 + row) * (3 * EMB) + h * HD + ch * 8);
    }
    #pragma unroll
    for (int it = 0; it < 2; it++) {
        int idx = it * 256 + tid;
        int row = idx >> 3, ch = idx & 7;
        uint32_t soff = sw128((uint32_t)(row * 128 + ch * 16));
        const __half* gk = base + (size_t)row * (3 * EMB) + EMB + h * HD + ch * 8;
        CP16(sb + 16384 + soff, gk);
        CP16(sb + 32768 + soff, gk + EMB);
    }
    CP_COMMIT();
    CP_WAIT0();
    __syncthreads();

    uint32_t qf[4][4];
    #pragma unroll
    for (int kk = 0; kk < 4; kk++) {
        int row = w * 16 + (lane & 15);
        uint32_t cbhi = (uint32_t)(kk * 2 + (lane >> 4));
        LDSM4(qf[kk], sb + (uint32_t)(row * 128) + ((cbhi ^ (row & 7)) << 4));
    }

    float o[8][4];
    #pragma unroll
    for (int i = 0; i < 8; i++)
        #pragma unroll
        for (int j = 0; j < 4; j++) o[i][j] = 0.f;
    float m0 = -INFINITY, m1 = -INFINITY, l0 = 0.f, l1 = 0.f;

    const int rbase = q0 + w * 16 + (lane >> 2);
    const int rmin = q0 + w * 16;
    const int nkv = (q0 >> 6) + 2;

    for (int t = 0; t < nkv; t++) {
        const int cur = t & 1;
        if (t + 1 < nkv) {
            const int k1 = (t + 1) * 64;
            const uint32_t kb = sb + 16384 + (uint32_t)((cur ^ 1) * 8192);
            const uint32_t vb = sb + 32768 + (uint32_t)((cur ^ 1) * 8192);
            #pragma unroll
            for (int it = 0; it < 2; it++) {
                int idx = it * 256 + tid;
                int row = idx >> 3, ch = idx & 7;
                uint32_t soff = sw128((uint32_t)(row * 128 + ch * 16));
                const __half* gk = base + (size_t)(k1 + row) * (3 * EMB) + EMB + h * HD + ch * 8;
                CP16(kb + soff, gk);
                CP16(vb + soff, gk + EMB);
            }
            CP_COMMIT();
        }
        const int k0t = t * 64;
        const bool active = (k0t <= rmin + 15);   // warp has ≥1 unmasked row in tile

        if (active) {
            const uint32_t sK = sb + 16384 + (uint32_t)(cur * 8192);
            const uint32_t sV = sb + 32768 + (uint32_t)(cur * 8192);

            float s[8][4];
            #pragma unroll
            for (int i = 0; i < 8; i++)
                #pragma unroll
                for (int j = 0; j < 4; j++) s[i][j] = 0.f;
            #pragma unroll
            for (int kk = 0; kk < 4; kk++) {
                #pragma unroll
                for (int g = 0; g < 4; g++) {
                    int nrow = g * 16 + ((lane >> 4) << 3) + (lane & 7);
                    uint32_t cbhi = (uint32_t)(kk * 2 + ((lane >> 3) & 1));
                    uint32_t kf[4];
                    LDSM4(kf, sK + (uint32_t)(nrow * 128) + ((cbhi ^ (nrow & 7)) << 4));
                    MMAF16(s[2 * g],     qf[kk], kf[0], kf[1]);
                    MMAF16(s[2 * g + 1], qf[kk], kf[2], kf[3]);
                }
            }
            #pragma unroll
            for (int i = 0; i < 8; i++)
                #pragma unroll
                for (int j = 0; j < 4; j++) s[i][j] *= 0.125f;

            if (k0t + 63 > rmin) {
                #pragma unroll
                for (int nf = 0; nf < 8; nf++) {
                    int colb = k0t + nf * 8 + ((lane & 3) << 1);
                    if (colb > rbase)         s[nf][0] = -INFINITY;
                    if (colb + 1 > rbase)     s[nf][1] = -INFINITY;
                    if (colb > rbase + 8)     s[nf][2] = -INFINITY;
                    if (colb + 1 > rbase + 8) s[nf][3] = -INFINITY;
                }
            }

            float mx0 = -INFINITY, mx1 = -INFINITY;
            #pragma unroll
            for (int nf = 0; nf < 8; nf++) {
                mx0 = fmaxf(mx0, fmaxf(s[nf][0], s[nf][1]));
                mx1 = fmaxf(mx1, fmaxf(s[nf][2], s[nf][3]));
            }
            mx0 = fmaxf(mx0, __shfl_xor_sync(0xffffffffu, mx0, 1));
            mx0 = fmaxf(mx0, __shfl_xor_sync(0xffffffffu, mx0, 2));
            mx1 = fmaxf(mx1, __shfl_xor_sync(0xffffffffu, mx1, 1));
            mx1 = fmaxf(mx1, __shfl_xor_sync(0xffffffffu, mx1, 2));
            const float mn0 = fmaxf(m0, mx0), mn1 = fmaxf(m1, mx1);
            const float c0 = __expf(m0 - mn0), c1 = __expf(m1 - mn1);
            float sum0 = 0.f, sum1 = 0.f;
            #pragma unroll
            for (int nf = 0; nf < 8; nf++) {
                s[nf][0] = __expf(s[nf][0] - mn0);
                s[nf][1] = __expf(s[nf][1] - mn0);
                s[nf][2] = __expf(s[nf][2] - mn1);
                s[nf][3] = __expf(s[nf][3] - mn1);
                sum0 += s[nf][0] + s[nf][1];
                sum1 += s[nf][2] + s[nf][3];
            }
            sum0 += __shfl_xor_sync(0xffffffffu, sum0, 1);
            sum0 += __shfl_xor_sync(0xffffffffu, sum0, 2);
            sum1 += __shfl_xor_sync(0xffffffffu, sum1, 1);
            sum1 += __shfl_xor_sync(0xffffffffu, sum1, 2);
            l0 = l0 * c0 + sum0;
            l1 = l1 * c1 + sum1;
            m0 = mn0;
            m1 = mn1;
            #pragma unroll
            for (int nf = 0; nf < 8; nf++) {
                o[nf][0] *= c0; o[nf][1] *= c0;
                o[nf][2] *= c1; o[nf][3] *= c1;
            }

            #pragma unroll
            for (int kk = 0; kk < 4; kk++) {
                uint32_t pf[4];
                pf[0] = pack_f16(s[2 * kk][0],     s[2 * kk][1]);
                pf[1] = pack_f16(s[2 * kk][2],     s[2 * kk][3]);
                pf[2] = pack_f16(s[2 * kk + 1][0], s[2 * kk + 1][1]);
                pf[3] = pack_f16(s[2 * kk + 1][2], s[2 * kk + 1][3]);
                #pragma unroll
                for (int dg = 0; dg < 4; dg++) {
                    int row = kk * 16 + (((lane >> 3) & 1) << 3) + (lane & 7);
                    int cole = dg * 16 + ((lane >> 4) << 3);
                    uint32_t vf[4];
                    LDSM4T(vf, sV + sw128((uint32_t)(row * 128 + cole * 2)));
                    MMAF16(o[2 * dg],     pf, vf[0], vf[1]);
                    MMAF16(o[2 * dg + 1], pf, vf[2], vf[3]);
                }
            }
        }
        if (t + 1 < nkv) {
            CP_WAIT0();
            __syncthreads();
        }
    }

    const float li0 = 1.f / l0, li1 = 1.f / l1;
    const int row0 = q0 + w * 16 + (lane >> 2);
    #pragma unroll
    for (int nf = 0; nf < 8; nf++) {
        int col = h * HD + nf * 8 + ((lane & 3) << 1);
        *(uint32_t*)(Hout + (size_t)(b * SEQ + row0) * EMB + col) =
            pack_f16(o[nf][0] * li0, o[nf][1] * li0);
        *(uint32_t*)(Hout + (size_t)(b * SEQ + row0 + 8) * EMB + col) =
            pack_f16(o[nf][2] * li1, o[nf][3] * li1);
    }
}

// ============ residual add + layernorm, one pass, regs-resident ============
__global__ __launch_bounds__(256) void ln_kernel(
    const float* __restrict__ x, const float* __restrict__ hres,
    const float* __restrict__ g, const float* __restrict__ be,
    float* __restrict__ out, __half* __restrict__ out16)
{
    __shared__ float red[16];
    const int row = blockIdx.x;
    const int tid = threadIdx.x;
    const float* xr = x + (size_t)row * EMB;
    const float* hr = hres + (size_t)row * EMB;

    float4 xv = *(const float4*)(xr + tid * 4);
    float4 hv = *(const float4*)(hr + tid * 4);
    float v0 = xv.x + hv.x, v1 = xv.y + hv.y, v2 = xv.z + hv.z, v3 = xv.w + hv.w;

    float s = v0 + v1 + v2 + v3;
    float q = v0 * v0 + v1 * v1 + v2 * v2 + v3 * v3;
    #pragma unroll
    for (int o = 16; o; o >>= 1) {
        s += __shfl_down_sync(0xffffffffu, s, o);
        q += __shfl_down_sync(0xffffffffu, q, o);
    }
    if ((tid & 31) == 0) { red[tid >> 5] = s; red[8 + (tid >> 5)] = q; }
    __syncthreads();
    if (tid < 8) {
        s = red[tid];
        q = red[8 + tid];
        #pragma unroll
        for (int o = 4; o; o >>= 1) {
            s += __shfl_down_sync(0xffu, s, o);
            q += __shfl_down_sync(0xffu, q, o);
        }
        if (tid == 0) { red[0] = s; red[8] = q; }
    }
    __syncthreads();
    const float mu = red[0] * (1.f / EMB);
    const float var = red[8] * (1.f / EMB) - mu * mu;
    const float rstd = rsqrtf(var + LN_EPS);

    float4 gv = *(const float4*)(g + tid * 4);
    float4 bv = *(const float4*)(be + tid * 4);
    float o0 = (v0 - mu) * rstd * gv.x + bv.x;
    float o1 = (v1 - mu) * rstd * gv.y + bv.y;
    float o2 = (v2 - mu) * rstd * gv.z + bv.z;
    float o3 = (v3 - mu) * rstd * gv.w + bv.w;
    *(float4*)(out + (size_t)row * EMB + tid * 4) = make_float4(o0, o1, o2, o3);
    if (out16) {
        *(uint2*)(out16 + (size_t)row * EMB + tid * 4) =
            make_uint2(pack_f16(o0, o1), pack_f16(o2, o3));
    }
}

// ================= launch =================
extern "C" void kernel_launch(void* const* d_in, const int* in_sizes, int n_in,
                              void* d_out, int out_size)
{
    const float* x     = (const float*)d_in[0];
    const float* W_qkv = (const float*)d_in[1];
    const float* b_qkv = (const float*)d_in[2];
    const float* W_out = (const float*)d_in[3];
    const float* b_out = (const float*)d_in[4];
    const float* g1    = (const float*)d_in[5];
    const float* be1   = (const float*)d_in[6];
    const float* W_ff1 = (const float*)d_in[7];
    const float* b_ff1 = (const float*)d_in[8];
    const float* W_ff2 = (const float*)d_in[9];
    const float* b_ff2 = (const float*)d_in[10];
    const float* g2    = (const float*)d_in[11];
    const float* be2   = (const float*)d_in[12];
    float* out = (float*)d_out;

    __half *x16, *qkv16, *attn16, *x116, *ffh16;
    float *tmp, *x1;
    cudaGetSymbolAddress((void**)&x16,    g_x16);
    cudaGetSymbolAddress((void**)&qkv16,  g_qkv16);
    cudaGetSymbolAddress((void**)&attn16, g_attn16);
    cudaGetSymbolAddress((void**)&x116,   g_x116);
    cudaGetSymbolAddress((void**)&ffh16,  g_ffh16);
    cudaGetSymbolAddress((void**)&tmp,    g_tmp);
    cudaGetSymbolAddress((void**)&x1,     g_x1);
    __half *wq, *wo, *w1, *w2;
    cudaGetSymbolAddress((void**)&wq, wt_qkv16);
    cudaGetSymbolAddress((void**)&wo, wt_out16);
    cudaGetSymbolAddress((void**)&w1, wt_ff116);
    cudaGetSymbolAddress((void**)&w2, wt_ff216);

    cudaFuncSetAttribute(gemm_f16, cudaFuncAttributeMaxDynamicSharedMemorySize, GEMM_SMEM);
    cudaFuncSetAttribute(attn_mma, cudaFuncAttributeMaxDynamicSharedMemorySize, 49152);

    // 0) all conversions in one launch
    conv_all<<<12288, 256>>>(W_qkv, wq, W_out, wo, W_ff1, w1, W_ff2, w2, x, x16);

    // 1) qkv = x @ W_qkv + b_qkv  (fp16 out only)
    gemm_f16<<<dim3(3 * EMB / 256, MROWS / 128), 512, GEMM_SMEM>>>(
        x16, wq, b_qkv, (float*)0, qkv16, MROWS, 3 * EMB, EMB, 0);

    // 2) causal flash attention (fp16 -> fp16)
    attn_mma<<<dim3(SEQ / 128, NH, BATCH), 256, 49152>>>(qkv16, attn16);

    // 3) proj = attn @ W_out + b_out  (fp32 out)
    gemm_f16<<<dim3(EMB / 256, MROWS / 128), 512, GEMM_SMEM>>>(
        attn16, wo, b_out, tmp, (__half*)0, MROWS, EMB, EMB, 0);

    // 4) x1 = LN(x + proj)  (fp32 + fp16)
    ln_kernel<<<MROWS, 256>>>(x, tmp, g1, be1, x1, x116);

    // 5) ffh = relu(x1 @ W_ff1 + b_ff1)  (fp16 out only)
    gemm_f16<<<dim3(FF_DIM / 256, MROWS / 128), 512, GEMM_SMEM>>>(
        x116, w1, b_ff1, (float*)0, ffh16, MROWS, FF_DIM, EMB, 1);

    // 6) ff = ffh @ W_ff2 + b_ff2  (fp32 out)
    gemm_f16<<<dim3(EMB / 256, MROWS / 128), 512, GEMM_SMEM>>>(
        ffh16, w2, b_ff2, tmp, (__half*)0, MROWS, EMB, FF_DIM, 0);

    // 7) out = LN(x1 + ff)
    ln_kernel<<<MROWS, 256>>>(x1, tmp, g2, be2, out, (__half*)0);
}

// round 11
// speedup vs baseline: 7.8759x; 1.0042x over previous
#include <cuda_runtime.h>
#include <cuda_fp16.h>
#include <math.h>
#include <stdint.h>

#define EMB 1024
#define SEQ 2048
#define BATCH 2
#define NH 16
#define HD 64
#define FF_DIM 2048
#define MROWS (BATCH * SEQ)   // 4096
#define LN_EPS 1e-5f

// ================= helpers (baseline PTX ISA, sm_80-era) =================
__device__ __forceinline__ uint32_t smem_u32(const void* p) {
    uint32_t a;
    asm("{ .reg .u64 t; cvta.to.shared.u64 t, %1; cvt.u32.u64 %0, t; }" : "=r"(a) : "l"(p));
    return a;
}
__device__ __forceinline__ uint32_t sw128(uint32_t off) { return off ^ ((off >> 3) & 0x70); }

#define CP16(dst, src) asm volatile("cp.async.cg.shared.global [%0], [%1], 16;" :: "r"(dst), "l"(src) : "memory")
#define CP_COMMIT()    asm volatile("cp.async.commit_group;" ::: "memory")
#define CP_WAIT0()     asm volatile("cp.async.wait_group 0;" ::: "memory")
#define CP_WAIT1()     asm volatile("cp.async.wait_group 1;" ::: "memory")

#define LDSM4(r, addr) \
    asm volatile("ldmatrix.sync.aligned.m8n8.x4.shared.b16 {%0,%1,%2,%3}, [%4];" \
        : "=r"((r)[0]), "=r"((r)[1]), "=r"((r)[2]), "=r"((r)[3]) : "r"(addr))
#define LDSM4T(r, addr) \
    asm volatile("ldmatrix.sync.aligned.m8n8.x4.trans.shared.b16 {%0,%1,%2,%3}, [%4];" \
        : "=r"((r)[0]), "=r"((r)[1]), "=r"((r)[2]), "=r"((r)[3]) : "r"(addr))

#define MMAF16(d, a, b0, b1) \
    asm volatile("mma.sync.aligned.m16n8k16.row.col.f32.f16.f16.f32 " \
        "{%0,%1,%2,%3},{%4,%5,%6,%7},{%8,%9},{%0,%1,%2,%3};" \
        : "+f"((d)[0]), "+f"((d)[1]), "+f"((d)[2]), "+f"((d)[3]) \
        : "r"((a)[0]), "r"((a)[1]), "r"((a)[2]), "r"((a)[3]), "r"(b0), "r"(b1))

__device__ __forceinline__ uint32_t pack_f16(float a, float b) {
    __half2 t = __floats2half2_rn(a, b);
    return *(uint32_t*)&t;
}

// ================= scratch =================
__device__ __half g_x16[(size_t)MROWS * EMB];
__device__ __half g_qkv16[(size_t)MROWS * 3 * EMB];
__device__ __half g_attn16[(size_t)MROWS * EMB];
__device__ __half g_x116[(size_t)MROWS * EMB];
__device__ __half g_ffh16[(size_t)MROWS * FF_DIM];
__device__ float  g_tmp[(size_t)MROWS * EMB];
__device__ float  g_x1[(size_t)MROWS * EMB];
__device__ __half wt_qkv16[(size_t)3 * EMB * EMB];
__device__ __half wt_out16[(size_t)EMB * EMB];
__device__ __half wt_ff116[(size_t)FF_DIM * EMB];
__device__ __half wt_ff216[(size_t)EMB * FF_DIM];

// ============ merged conversions: 4 weight transposes + x fp32->fp16 ============
__global__ __launch_bounds__(256) void conv_all(
    const float* __restrict__ Wq, __half* __restrict__ Tq,
    const float* __restrict__ Wo, __half* __restrict__ To,
    const float* __restrict__ W1, __half* __restrict__ T1,
    const float* __restrict__ W2, __half* __restrict__ T2,
    const float* __restrict__ x, __half* __restrict__ x16)
{
    const int bid = blockIdx.x;
    const int tx = threadIdx.x & 31, ty = threadIdx.x >> 5;

    if (bid >= 8192) {
        int i = (bid - 8192) * 256 + threadIdx.x;
        float4 v = *(const float4*)(x + (size_t)i * 4);
        *(uint2*)(x16 + (size_t)i * 4) = make_uint2(pack_f16(v.x, v.y), pack_f16(v.z, v.w));
        return;
    }

    const float* W; __half* T;
    int K, N, bx, by;
    if (bid < 3072)      { W = Wq; T = Tq; K = 1024; N = 3072; bx = bid % 96;          by = bid / 96; }
    else if (bid < 4096) { W = Wo; T = To; K = 1024; N = 1024; bx = (bid - 3072) % 32; by = (bid - 3072) / 32; }
    else if (bid < 6144) { W = W1; T = T1; K = 1024; N = 2048; bx = (bid - 4096) % 64; by = (bid - 4096) / 64; }
    else                 { W = W2; T = T2; K = 2048; N = 1024; bx = (bid - 6144) % 32; by = (bid - 6144) / 32; }

    __shared__ float sm[32][33];
    const int n0 = bx * 32, k0 = by * 32;
    #pragma unroll
    for (int i = 0; i < 4; i++)
        sm[ty + i * 8][tx] = W[(size_t)(k0 + ty + i * 8) * N + n0 + tx];
    __syncthreads();
    #pragma unroll
    for (int i = 0; i < 4; i++) {
        int nl = ty + i * 8;
        T[(size_t)(n0 + nl) * K + k0 + tx] = __float2half(sm[tx][nl]);
    }
}

// ============ fp16 HMMA GEMM: C = A[M,K] @ B[N,K]^T + bias ============
// CTA tile 128x256, BK=64, 3-stage cp.async. 256 threads (8 warps, 2Mx4N),
// warp tile 64x64, register-double-buffered fragments.
#define GT_STAGE 49152        // A 16K @0 | B 32K @16K
#define GOFF_B 16384
#define GEMM_SMEM (3 * GT_STAGE)

__device__ __forceinline__ void g_cpA(
    const __half* __restrict__ A, uint32_t st, int K, int m0, int kc, int tid)
{
    #pragma unroll
    for (int it = 0; it < 4; it++) {
        int idx = it * 256 + tid;
        int row = idx >> 3, ch = idx & 7;
        CP16(st + sw128((uint32_t)(row * 128 + ch * 16)),
             A + (size_t)(m0 + row) * K + kc + ch * 8);
    }
}
__device__ __forceinline__ void g_cpB(
    const __half* __restrict__ B, uint32_t st, int K, int n0, int kc, int tid)
{
    #pragma unroll
    for (int it = 0; it < 8; it++) {
        int idx = it * 256 + tid;
        int row = idx >> 3, ch = idx & 7;
        CP16(st + GOFF_B + sw128((uint32_t)(row * 128 + ch * 16)),
             B + (size_t)(n0 + row) * K + kc + ch * 8);
    }
}

__device__ __forceinline__ void ld_afrag(
    uint32_t (&af)[4][4], uint32_t s0, int kk, int wm, int lane)
{
    #pragma unroll
    for (int mt = 0; mt < 4; mt++) {
        int row = wm + mt * 16 + (lane & 15);
        uint32_t cbhi = (uint32_t)(kk * 2 + (lane >> 4));
        LDSM4(af[mt], s0 + (uint32_t)(row * 128) + ((cbhi ^ (row & 7)) << 4));
    }
}
__device__ __forceinline__ void ld_bfrag(
    uint32_t (&bf)[4][4], uint32_t s0, int kk, int wn, int lane)
{
    #pragma unroll
    for (int g = 0; g < 4; g++) {
        int nrow = wn + g * 16 + ((lane >> 4) << 3) + (lane & 7);
        uint32_t cbhi = (uint32_t)(kk * 2 + ((lane >> 3) & 1));
        LDSM4(bf[g], s0 + GOFF_B + (uint32_t)(nrow * 128) + ((cbhi ^ (nrow & 7)) << 4));
    }
}

__global__ __launch_bounds__(256, 1) void gemm_f16(
    const __half* __restrict__ A, const __half* __restrict__ B,
    const float* __restrict__ bias, float* __restrict__ C32,
    __half* __restrict__ C16, int M, int N, int K, int relu)
{
    extern __shared__ char sm[];
    const uint32_t smb = smem_u32(sm);
    const int tid = threadIdx.x, wid = tid >> 5, lane = tid & 31;
    const int m0 = blockIdx.y * 128, n0 = blockIdx.x * 256;
    const int wm = (wid & 1) * 64, wn = (wid >> 1) * 64;
    const int NC = K >> 6;

    float acc[4][8][4];
    #pragma unroll
    for (int i = 0; i < 4; i++)
        #pragma unroll
        for (int j = 0; j < 8; j++)
            #pragma unroll
            for (int q = 0; q < 4; q++) acc[i][j][q] = 0.f;

    g_cpA(A, smb, K, m0, 0, tid);
    g_cpB(B, smb, K, n0, 0, tid);
    CP_COMMIT();
    g_cpA(A, smb + GT_STAGE, K, m0, 64, tid);
    g_cpB(B, smb + GT_STAGE, K, n0, 64, tid);
    CP_COMMIT();

    uint32_t af[2][4][4], bf[2][4][4];
    int sidx = 0;
    for (int c = 0; c < NC; c++) {
        if (c + 2 < NC) CP_WAIT1(); else CP_WAIT0();
        __syncthreads();
        if (c + 2 < NC) {
            int ns = sidx + 2; if (ns >= 3) ns -= 3;
            const uint32_t st = smb + (uint32_t)ns * GT_STAGE;
            g_cpA(A, st, K, m0, (c + 2) << 6, tid);
            g_cpB(B, st, K, n0, (c + 2) << 6, tid);
            CP_COMMIT();
        }
        const uint32_t s0 = smb + (uint32_t)sidx * GT_STAGE;

        // register-double-buffered fragment pipeline over 4 k16 steps
        ld_afrag(af[0], s0, 0, wm, lane);
        ld_bfrag(bf[0], s0, 0, wn, lane);
        #pragma unroll
        for (int kk = 0; kk < 4; kk++) {
            const int cur = kk & 1;
            if (kk < 3) {
                ld_afrag(af[cur ^ 1], s0, kk + 1, wm, lane);
                ld_bfrag(bf[cur ^ 1], s0, kk + 1, wn, lane);
            }
            #pragma unroll
            for (int mt = 0; mt < 4; mt++) {
                #pragma unroll
                for (int g = 0; g < 4; g++) {
                    MMAF16(acc[mt][2 * g],     af[cur][mt], bf[cur][g][0], bf[cur][g][1]);
                    MMAF16(acc[mt][2 * g + 1], af[cur][mt], bf[cur][g][2], bf[cur][g][3]);
                }
            }
        }
        if (++sidx >= 3) sidx -= 3;
    }

    // epilogue: bias + optional relu; fp32 and/or fp16 outputs
    #pragma unroll
    for (int mt = 0; mt < 4; mt++) {
        #pragma unroll
        for (int nt = 0; nt < 8; nt++) {
            int r0 = m0 + wm + mt * 16 + (lane >> 2);
            int col = n0 + wn + nt * 8 + (lane & 3) * 2;
            float2 bb = *(const float2*)(bias + col);
            float v0 = acc[mt][nt][0] + bb.x;
            float v1 = acc[mt][nt][1] + bb.y;
            float v2 = acc[mt][nt][2] + bb.x;
            float v3 = acc[mt][nt][3] + bb.y;
            if (relu) {
                v0 = fmaxf(v0, 0.f); v1 = fmaxf(v1, 0.f);
                v2 = fmaxf(v2, 0.f); v3 = fmaxf(v3, 0.f);
            }
            if (C32) {
                *(float2*)(C32 + (size_t)r0 * N + col) = make_float2(v0, v1);
                *(float2*)(C32 + (size_t)(r0 + 8) * N + col) = make_float2(v2, v3);
            }
            if (C16) {
                *(uint32_t*)(C16 + (size_t)r0 * N + col) = pack_f16(v0, v1);
                *(uint32_t*)(C16 + (size_t)(r0 + 8) * N + col) = pack_f16(v2, v3);
            }
        }
    }
}

// ================= flash attention: fp16 in/out, LPT order, masked-warp skip ========
__global__ __launch_bounds__(256, 2) void attn_mma(
    const __half* __restrict__ qkv, __half* __restrict__ Hout)
{
    extern __shared__ char sma[];
    const uint32_t sb = smem_u32(sma);

    const int tid = threadIdx.x, lane = tid & 31, w = tid >> 5;
    const int qb = gridDim.x - 1 - blockIdx.x;   // LPT: longest CTAs first
    const int h = blockIdx.y, b = blockIdx.z;
    const int q0 = qb * 128;
    const __half* base = qkv + (size_t)b * SEQ * 3 * EMB;

    #pragma unroll
    for (int it = 0; it < 4; it++) {
        int idx = it * 256 + tid;
        int row = idx >> 3, ch = idx & 7;
        CP16(sb + sw128((uint32_t)(row * 128 + ch * 16)),
             base + (size_t)(q0 + row) * (3 * EMB) + h * HD + ch * 8);
    }
    #pragma unroll
    for (int it = 0; it < 2; it++) {
        int idx = it * 256 + tid;
        int row = idx >> 3, ch = idx & 7;
        uint32_t soff = sw128((uint32_t)(row * 128 + ch * 16));
        const __half* gk = base + (size_t)row * (3 * EMB) + EMB + h * HD + ch * 8;
        CP16(sb + 16384 + soff, gk);
        CP16(sb + 32768 + soff, gk + EMB);
    }
    CP_COMMIT();
    CP_WAIT0();
    __syncthreads();

    uint32_t qf[4][4];
    #pragma unroll
    for (int kk = 0; kk < 4; kk++) {
        int row = w * 16 + (lane & 15);
        uint32_t cbhi = (uint32_t)(kk * 2 + (lane >> 4));
        LDSM4(qf[kk], sb + (uint32_t)(row * 128) + ((cbhi ^ (row & 7)) << 4));
    }

    float o[8][4];
    #pragma unroll
    for (int i = 0; i < 8; i++)
        #pragma unroll
        for (int j = 0; j < 4; j++) o[i][j] = 0.f;
    float m0 = -INFINITY, m1 = -INFINITY, l0 = 0.f, l1 = 0.f;

    const int rbase = q0 + w * 16 + (lane >> 2);
    const int rmin = q0 + w * 16;
    const int nkv = (q0 >> 6) + 2;

    for (int t = 0; t < nkv; t++) {
        const int cur = t & 1;
        if (t + 1 < nkv) {
            const int k1 = (t + 1) * 64;
            const uint32_t kb = sb + 16384 + (uint32_t)((cur ^ 1) * 8192);
            const uint32_t vb = sb + 32768 + (uint32_t)((cur ^ 1) * 8192);
            #pragma unroll
            for (int it = 0; it < 2; it++) {
                int idx = it * 256 + tid;
                int row = idx >> 3, ch = idx & 7;
                uint32_t soff = sw128((uint32_t)(row * 128 + ch * 16));
                const __half* gk = base + (size_t)(k1 + row) * (3 * EMB) + EMB + h * HD + ch * 8;
                CP16(kb + soff, gk);
                CP16(vb + soff, gk + EMB);
            }
            CP_COMMIT();
        }
        const int k0t = t * 64;
        const bool active = (k0t <= rmin + 15);

        if (active) {
            const uint32_t sK = sb + 16384 + (uint32_t)(cur * 8192);
            const uint32_t sV = sb + 32768 + (uint32_t)(cur * 8192);

            float s[8][4];
            #pragma unroll
            for (int i = 0; i < 8; i++)
                #pragma unroll
                for (int j = 0; j < 4; j++) s[i][j] = 0.f;
            #pragma unroll
            for (int kk = 0; kk < 4; kk++) {
                #pragma unroll
                for (int g = 0; g < 4; g++) {
                    int nrow = g * 16 + ((lane >> 4) << 3) + (lane & 7);
                    uint32_t cbhi = (uint32_t)(kk * 2 + ((lane >> 3) & 1));
                    uint32_t kf[4];
                    LDSM4(kf, sK + (uint32_t)(nrow * 128) + ((cbhi ^ (nrow & 7)) << 4));
                    MMAF16(s[2 * g],     qf[kk], kf[0], kf[1]);
                    MMAF16(s[2 * g + 1], qf[kk], kf[2], kf[3]);
                }
            }
            #pragma unroll
            for (int i = 0; i < 8; i++)
                #pragma unroll
                for (int j = 0; j < 4; j++) s[i][j] *= 0.125f;

            if (k0t + 63 > rmin) {
                #pragma unroll
                for (int nf = 0; nf < 8; nf++) {
                    int colb = k0t + nf * 8 + ((lane & 3) << 1);
                    if (colb > rbase)         s[nf][0] = -INFINITY;
                    if (colb + 1 > rbase)     s[nf][1] = -INFINITY;
                    if (colb > rbase + 8)     s[nf][2] = -INFINITY;
                    if (colb + 1 > rbase + 8) s[nf][3] = -INFINITY;
                }
            }

            float mx0 = -INFINITY, mx1 = -INFINITY;
            #pragma unroll
            for (int nf = 0; nf < 8; nf++) {
                mx0 = fmaxf(mx0, fmaxf(s[nf][0], s[nf][1]));
                mx1 = fmaxf(mx1, fmaxf(s[nf][2], s[nf][3]));
            }
            mx0 = fmaxf(mx0, __shfl_xor_sync(0xffffffffu, mx0, 1));
            mx0 = fmaxf(mx0, __shfl_xor_sync(0xffffffffu, mx0, 2));
            mx1 = fmaxf(mx1, __shfl_xor_sync(0xffffffffu, mx1, 1));
            mx1 = fmaxf(mx1, __shfl_xor_sync(0xffffffffu, mx1, 2));
            const float mn0 = fmaxf(m0, mx0), mn1 = fmaxf(m1, mx1);
            const float c0 = __expf(m0 - mn0), c1 = __expf(m1 - mn1);
            float sum0 = 0.f, sum1 = 0.f;
            #pragma unroll
            for (int nf = 0; nf < 8; nf++) {
                s[nf][0] = __expf(s[nf][0] - mn0);
                s[nf][1] = __expf(s[nf][1] - mn0);
                s[nf][2] = __expf(s[nf][2] - mn1);
                s[nf][3] = __expf(s[nf][3] - mn1);
                sum0 += s[nf][0] + s[nf][1];
                sum1 += s[nf][2] + s[nf][3];
            }
            sum0 += __shfl_xor_sync(0xffffffffu, sum0, 1);
            sum0 += __shfl_xor_sync(0xffffffffu, sum0, 2);
            sum1 += __shfl_xor_sync(0xffffffffu, sum1, 1);
            sum1 += __shfl_xor_sync(0xffffffffu, sum1, 2);
            l0 = l0 * c0 + sum0;
            l1 = l1 * c1 + sum1;
            m0 = mn0;
            m1 = mn1;
            #pragma unroll
            for (int nf = 0; nf < 8; nf++) {
                o[nf][0] *= c0; o[nf][1] *= c0;
                o[nf][2] *= c1; o[nf][3] *= c1;
            }

            #pragma unroll
            for (int kk = 0; kk < 4; kk++) {
                uint32_t pf[4];
                pf[0] = pack_f16(s[2 * kk][0],     s[2 * kk][1]);
                pf[1] = pack_f16(s[2 * kk][2],     s[2 * kk][3]);
                pf[2] = pack_f16(s[2 * kk + 1][0], s[2 * kk + 1][1]);
                pf[3] = pack_f16(s[2 * kk + 1][2], s[2 * kk + 1][3]);
                #pragma unroll
                for (int dg = 0; dg < 4; dg++) {
                    int row = kk * 16 + (((lane >> 3) & 1) << 3) + (lane & 7);
                    int cole = dg * 16 + ((lane >> 4) << 3);
                    uint32_t vf[4];
                    LDSM4T(vf, sV + sw128((uint32_t)(row * 128 + cole * 2)));
                    MMAF16(o[2 * dg],     pf, vf[0], vf[1]);
                    MMAF16(o[2 * dg + 1], pf, vf[2], vf[3]);
                }
            }
        }
        if (t + 1 < nkv) {
            CP_WAIT0();
            __syncthreads();
        }
    }

    const float li0 = 1.f / l0, li1 = 1.f / l1;
    const int row0 = q0 + w * 16 + (lane >> 2);
    #pragma unroll
    for (int nf = 0; nf < 8; nf++) {
        int col = h * HD + nf * 8 + ((lane & 3) << 1);
        *(uint32_t*)(Hout + (size_t)(b * SEQ + row0) * EMB + col) =
            pack_f16(o[nf][0] * li0, o[nf][1] * li0);
        *(uint32_t*)(Hout + (size_t)(b * SEQ + row0 + 8) * EMB + col) =
            pack_f16(o[nf][2] * li1, o[nf][3] * li1);
    }
}

// ============ residual add + layernorm, one pass, regs-resident ============
__global__ __launch_bounds__(256) void ln_kernel(
    const float* __restrict__ x, const float* __restrict__ hres,
    const float* __restrict__ g, const float* __restrict__ be,
    float* __restrict__ out, __half* __restrict__ out16)
{
    __shared__ float red[16];
    const int row = blockIdx.x;
    const int tid = threadIdx.x;
    const float* xr = x + (size_t)row * EMB;
    const float* hr = hres + (size_t)row * EMB;

    float4 xv = *(const float4*)(xr + tid * 4);
    float4 hv = *(const float4*)(hr + tid * 4);
    float v0 = xv.x + hv.x, v1 = xv.y + hv.y, v2 = xv.z + hv.z, v3 = xv.w + hv.w;

    float s = v0 + v1 + v2 + v3;
    float q = v0 * v0 + v1 * v1 + v2 * v2 + v3 * v3;
    #pragma unroll
    for (int o = 16; o; o >>= 1) {
        s += __shfl_down_sync(0xffffffffu, s, o);
        q += __shfl_down_sync(0xffffffffu, q, o);
    }
    if ((tid & 31) == 0) { red[tid >> 5] = s; red[8 + (tid >> 5)] = q; }
    __syncthreads();
    if (tid < 8) {
        s = red[tid];
        q = red[8 + tid];
        #pragma unroll
        for (int o = 4; o; o >>= 1) {
            s += __shfl_down_sync(0xffu, s, o);
            q += __shfl_down_sync(0xffu, q, o);
        }
        if (tid == 0) { red[0] = s; red[8] = q; }
    }
    __syncthreads();
    const float mu = red[0] * (1.f / EMB);
    const float var = red[8] * (1.f / EMB) - mu * mu;
    const float rstd = rsqrtf(var + LN_EPS);

    float4 gv = *(const float4*)(g + tid * 4);
    float4 bv = *(const float4*)(be + tid * 4);
    float o0 = (v0 - mu) * rstd * gv.x + bv.x;
    float o1 = (v1 - mu) * rstd * gv.y + bv.y;
    float o2 = (v2 - mu) * rstd * gv.z + bv.z;
    float o3 = (v3 - mu) * rstd * gv.w + bv.w;
    *(float4*)(out + (size_t)row * EMB + tid * 4) = make_float4(o0, o1, o2, o3);
    if (out16) {
        *(uint2*)(out16 + (size_t)row * EMB + tid * 4) =
            make_uint2(pack_f16(o0, o1), pack_f16(o2, o3));
    }
}

// ================= launch =================
extern "C" void kernel_launch(void* const* d_in, const int* in_sizes, int n_in,
                              void* d_out, int out_size)
{
    const float* x     = (const float*)d_in[0];
    const float* W_qkv = (const float*)d_in[1];
    const float* b_qkv = (const float*)d_in[2];
    const float* W_out = (const float*)d_in[3];
    const float* b_out = (const float*)d_in[4];
    const float* g1    = (const float*)d_in[5];
    const float* be1   = (const float*)d_in[6];
    const float* W_ff1 = (const float*)d_in[7];
    const float* b_ff1 = (const float*)d_in[8];
    const float* W_ff2 = (const float*)d_in[9];
    const float* b_ff2 = (const float*)d_in[10];
    const float* g2    = (const float*)d_in[11];
    const float* be2   = (const float*)d_in[12];
    float* out = (float*)d_out;

    __half *x16, *qkv16, *attn16, *x116, *ffh16;
    float *tmp, *x1;
    cudaGetSymbolAddress((void**)&x16,    g_x16);
    cudaGetSymbolAddress((void**)&qkv16,  g_qkv16);
    cudaGetSymbolAddress((void**)&attn16, g_attn16);
    cudaGetSymbolAddress((void**)&x116,   g_x116);
    cudaGetSymbolAddress((void**)&ffh16,  g_ffh16);
    cudaGetSymbolAddress((void**)&tmp,    g_tmp);
    cudaGetSymbolAddress((void**)&x1,     g_x1);
    __half *wq, *wo, *w1, *w2;
    cudaGetSymbolAddress((void**)&wq, wt_qkv16);
    cudaGetSymbolAddress((void**)&wo, wt_out16);
    cudaGetSymbolAddress((void**)&w1, wt_ff116);
    cudaGetSymbolAddress((void**)&w2, wt_ff216);

    cudaFuncSetAttribute(gemm_f16, cudaFuncAttributeMaxDynamicSharedMemorySize, GEMM_SMEM);
    cudaFuncSetAttribute(attn_mma, cudaFuncAttributeMaxDynamicSharedMemorySize, 49152);

    // 0) all conversions in one launch
    conv_all<<<12288, 256>>>(W_qkv, wq, W_out, wo, W_ff1, w1, W_ff2, w2, x, x16);

    // 1) qkv = x @ W_qkv + b_qkv  (fp16 out only)
    gemm_f16<<<dim3(3 * EMB / 256, MROWS / 128), 256, GEMM_SMEM>>>(
        x16, wq, b_qkv, (float*)0, qkv16, MROWS, 3 * EMB, EMB, 0);

    // 2) causal flash attention (fp16 -> fp16)
    attn_mma<<<dim3(SEQ / 128, NH, BATCH), 256, 49152>>>(qkv16, attn16);

    // 3) proj = attn @ W_out + b_out  (fp32 out)
    gemm_f16<<<dim3(EMB / 256, MROWS / 128), 256, GEMM_SMEM>>>(
        attn16, wo, b_out, tmp, (__half*)0, MROWS, EMB, EMB, 0);

    // 4) x1 = LN(x + proj)  (fp32 + fp16)
    ln_kernel<<<MROWS, 256>>>(x, tmp, g1, be1, x1, x116);

    // 5) ffh = relu(x1 @ W_ff1 + b_ff1)  (fp16 out only)
    gemm_f16<<<dim3(FF_DIM / 256, MROWS / 128), 256, GEMM_SMEM>>>(
        x116, w1, b_ff1, (float*)0, ffh16, MROWS, FF_DIM, EMB, 1);

    // 6) ff = ffh @ W_ff2 + b_ff2  (fp32 out)
    gemm_f16<<<dim3(EMB / 256, MROWS / 128), 256, GEMM_SMEM>>>(
        ffh16, w2, b_ff2, tmp, (__half*)0, MROWS, EMB, FF_DIM, 0);

    // 7) out = LN(x1 + ff)
    ln_kernel<<<MROWS, 256>>>(x1, tmp, g2, be2, out, (__half*)0);
}